// round 7
// baseline (speedup 1.0000x reference)
#include <cuda_runtime.h>
#include <cuda_bf16.h>
#include <cstdint>

// Problem constants
#define BATCH 4
#define SEQ   2048
#define DMODEL 1024
#define NHEAD 16
#define HDIM  64
#define MROWS (BATCH*SEQ)         // 8192

#define NEG_INF __int_as_float(0xff800000)

// ---------------- scratch (device globals; no allocation allowed) ----------
#define NELEM (8192*1024)
__device__ __nv_bfloat16 g_ah[NELEM],  g_al[NELEM];            // input q hi/lo
__device__ __nv_bfloat16 g_wh[4*1024*1024], g_wl[4*1024*1024]; // Wq,Wk,Wv,Wo hi/lo
__device__ __nv_bfloat16 g_qhh[NELEM], g_qhl[NELEM];           // Q heads (b,h,s,hd)
__device__ __nv_bfloat16 g_khh[NELEM], g_khl[NELEM];
__device__ __nv_bfloat16 g_vhh[NELEM], g_vhl[NELEM];
__device__ __nv_bfloat16 g_oh[NELEM],  g_ol[NELEM];            // attn out (b,s,d)
__device__ unsigned char g_mask[BATCH*SEQ];
__device__ int g_mode;

// ---------------- mask dtype detection + canonicalization ------------------
__global__ void detect_mask_kernel(const unsigned char* __restrict__ p) {
    __shared__ int s1, s3;
    if (threadIdx.x == 0) { s1 = 0; s3 = 0; }
    __syncthreads();
    int l1 = 0, l3 = 0;
    for (int i = threadIdx.x; i < BATCH*SEQ; i += blockDim.x) {
        unsigned char v = p[i];
        int m = i & 3;
        if (m == 1 && v) l1 = 1;
        if (m == 3 && v) l3 = 1;
    }
    if (l1) atomicOr(&s1, 1);
    if (l3) atomicOr(&s3, 1);
    __syncthreads();
    if (threadIdx.x == 0) g_mode = s1 ? 0 : (s3 ? 1 : 2);  // 0=u8, 1=f32, 2=i32
}

__global__ void convert_mask_kernel(const unsigned char* __restrict__ p) {
    int i = blockIdx.x * blockDim.x + threadIdx.x;
    if (i >= BATCH*SEQ) return;
    int mode = g_mode;
    unsigned char r;
    if (mode == 0)      r = (p[i] != 0);
    else if (mode == 1) r = (((const float*)p)[i] != 0.0f);
    else                r = (((const int*)p)[i] != 0);
    g_mask[i] = r;
}

// ---------------- fp32 -> bf16 hi/lo split kernels --------------------------
__device__ __forceinline__ void split4(float4 v, __nv_bfloat16* h, __nv_bfloat16* l) {
    float f[4] = {v.x, v.y, v.z, v.w};
    #pragma unroll
    for (int p = 0; p < 2; ++p) {
        __nv_bfloat162 hp, lp;
        hp.x = __float2bfloat16(f[2*p]);
        hp.y = __float2bfloat16(f[2*p+1]);
        lp.x = __float2bfloat16(f[2*p]   - __bfloat162float(hp.x));
        lp.y = __float2bfloat16(f[2*p+1] - __bfloat162float(hp.y));
        *(__nv_bfloat162*)(h + 2*p) = hp;
        *(__nv_bfloat162*)(l + 2*p) = lp;
    }
}

__global__ void split_kernel(const float* __restrict__ src,
                             __nv_bfloat16* __restrict__ hi,
                             __nv_bfloat16* __restrict__ lo, int n) {
    int i = (blockIdx.x * blockDim.x + threadIdx.x) * 4;
    if (i >= n) return;
    split4(*(const float4*)(src + i), hi + i, lo + i);
}

__global__ void split_w_kernel(const float* __restrict__ w0, const float* __restrict__ w1,
                               const float* __restrict__ w2, const float* __restrict__ w3,
                               __nv_bfloat16* __restrict__ hi, __nv_bfloat16* __restrict__ lo) {
    int z = blockIdx.z;
    const float* src = (z==0)?w0:(z==1)?w1:(z==2)?w2:w3;
    size_t off = (size_t)z * 1024 * 1024;
    int i = (blockIdx.x * blockDim.x + threadIdx.x) * 4;
    split4(*(const float4*)(src + i), hi + off + i, lo + off + i);
}

// ---------------- mma / ldmatrix / cp.async primitives ----------------------
__device__ __forceinline__ void mma16816(float* c, const uint32_t* a, const uint32_t* b) {
    asm volatile(
        "mma.sync.aligned.m16n8k16.row.col.f32.bf16.bf16.f32 "
        "{%0,%1,%2,%3}, {%4,%5,%6,%7}, {%8,%9}, {%0,%1,%2,%3};"
        : "+f"(c[0]), "+f"(c[1]), "+f"(c[2]), "+f"(c[3])
        : "r"(a[0]), "r"(a[1]), "r"(a[2]), "r"(a[3]), "r"(b[0]), "r"(b[1]));
}
__device__ __forceinline__ void ldm_x4(uint32_t* r, uint32_t addr) {
    asm volatile("ldmatrix.sync.aligned.m8n8.x4.shared.b16 {%0,%1,%2,%3}, [%4];"
                 : "=r"(r[0]), "=r"(r[1]), "=r"(r[2]), "=r"(r[3]) : "r"(addr));
}
__device__ __forceinline__ void ldm_x2(uint32_t* r, uint32_t addr) {
    asm volatile("ldmatrix.sync.aligned.m8n8.x2.shared.b16 {%0,%1}, [%2];"
                 : "=r"(r[0]), "=r"(r[1]) : "r"(addr));
}
__device__ __forceinline__ void ldm_x4t(uint32_t* r, uint32_t addr) {
    asm volatile("ldmatrix.sync.aligned.m8n8.x4.trans.shared.b16 {%0,%1,%2,%3}, [%4];"
                 : "=r"(r[0]), "=r"(r[1]), "=r"(r[2]), "=r"(r[3]) : "r"(addr));
}
#define CP16(dst, src) \
    asm volatile("cp.async.cg.shared.global [%0], [%1], 16;" :: "r"(dst), "l"(src))
#define CP_COMMIT() asm volatile("cp.async.commit_group;" ::: "memory")
#define CP_WAIT(n)  asm volatile("cp.async.wait_group %0;" :: "n"(n) : "memory")

// ---------------- GEMM: C = A @ W^T + bias (bf16x3, cp.async 3-stage) -------
#define GSTAGE 32768
#define NIT 32

template <bool SPLIT>
__global__ __launch_bounds__(256, 1) void gemm_cp_kernel(
    const __nv_bfloat16* __restrict__ Ahg, const __nv_bfloat16* __restrict__ Alg,
    const __nv_bfloat16* __restrict__ Whb, const __nv_bfloat16* __restrict__ Wlb, int woff,
    const float* b0, const float* b1, const float* b2,
    __nv_bfloat16* C0h, __nv_bfloat16* C0l,
    __nv_bfloat16* C1h, __nv_bfloat16* C1l,
    __nv_bfloat16* C2h, __nv_bfloat16* C2l,
    float* Cf)
{
    int z = blockIdx.z;
    const __nv_bfloat16* Wh = Whb + (size_t)(woff + z) * 1024 * 1024;
    const __nv_bfloat16* Wl = Wlb + (size_t)(woff + z) * 1024 * 1024;
    const float* bias = (z == 0) ? b0 : (z == 1) ? b1 : b2;
    __nv_bfloat16* Ch = (z == 0) ? C0h : (z == 1) ? C1h : C2h;
    __nv_bfloat16* Cl = (z == 0) ? C0l : (z == 1) ? C1l : C2l;

    extern __shared__ __align__(128) unsigned char smraw[];
    uint32_t sb = (uint32_t)__cvta_generic_to_shared(smraw);

    int t = threadIdx.x, lane = t & 31, warp = t >> 5;
    int wm = warp >> 2, wn = warp & 3;
    int m0 = blockIdx.y * 128, n0 = blockIdx.x * 128;

    int row = t >> 1, half = t & 1;
    const __nv_bfloat16* srcA = (half ? Alg : Ahg) + (size_t)(m0 + row) * 1024;
    const __nv_bfloat16* srcB = (half ? Wl : Wh)  + (size_t)(n0 + row) * 1024;
    uint32_t rxor = (uint32_t)((row & 7) << 4);
    uint32_t dA = sb + row * 128;

    auto issue = [&](int ch) {
        uint32_t base = dA + (uint32_t)(ch % 3) * GSTAGE;
        const __nv_bfloat16* sa = srcA + ch * 32;
        const __nv_bfloat16* sbp = srcB + ch * 32;
        #pragma unroll
        for (int j = 0; j < 4; ++j) {
            uint32_t c = (uint32_t)(half * 64 + j * 16) ^ rxor;
            CP16(base + c,         sa  + j * 8);
            CP16(base + 16384 + c, sbp + j * 8);
        }
    };

    float c[4][4][4] = {};
    uint32_t x = (uint32_t)((lane & 7) << 4);
    uint32_t arow = (uint32_t)(wm * 64 + (lane & 15));
    uint32_t acol = (uint32_t)((lane >> 4) << 4);
    uint32_t brow = (uint32_t)(wn * 32 + (lane & 7));
    uint32_t bcol = (uint32_t)(((lane >> 3) & 1) << 4);

    issue(0); CP_COMMIT();
    issue(1); CP_COMMIT();

    for (int it = 0; it < NIT; ++it) {
        if (it + 1 < NIT) { CP_WAIT(1); } else { CP_WAIT(0); }
        __syncthreads();
        if (it + 2 < NIT) { issue(it + 2); CP_COMMIT(); }

        uint32_t Abase = sb + (uint32_t)(it % 3) * GSTAGE;
        uint32_t Bbase = Abase + 16384;
        #pragma unroll
        for (int ks = 0; ks < 2; ++ks) {
            uint32_t ch = (uint32_t)(ks * 32) + acol;
            uint32_t afh[4][4], afl[4][4];
            #pragma unroll
            for (int mi = 0; mi < 4; ++mi) {
                uint32_t ra = Abase + (arow + mi * 16) * 128;
                ldm_x4(afh[mi], ra + (ch ^ x));
                ldm_x4(afl[mi], ra + ((ch + 64) ^ x));
            }
            uint32_t cb = (uint32_t)(ks * 32) + bcol;
            uint32_t bfh[4][2], bfl[4][2];
            #pragma unroll
            for (int ni = 0; ni < 4; ++ni) {
                uint32_t rb = Bbase + (brow + ni * 8) * 128;
                ldm_x2(bfh[ni], rb + (cb ^ x));
                ldm_x2(bfl[ni], rb + ((cb + 64) ^ x));
            }
            #pragma unroll
            for (int mi = 0; mi < 4; ++mi)
                #pragma unroll
                for (int ni = 0; ni < 4; ++ni) {
                    mma16816(c[mi][ni], afh[mi], bfh[ni]);
                    mma16816(c[mi][ni], afh[mi], bfl[ni]);
                    mma16816(c[mi][ni], afl[mi], bfh[ni]);
                }
        }
    }

    // epilogue
    int g = lane >> 2, cq = (lane & 3) * 2;
    #pragma unroll
    for (int mi = 0; mi < 4; ++mi) {
        int r0 = m0 + wm*64 + mi*16 + g;
        int r1 = r0 + 8;
        #pragma unroll
        for (int ni = 0; ni < 4; ++ni) {
            int col = n0 + wn*32 + ni*8 + cq;
            float b0v = __ldg(bias + col), b1v = __ldg(bias + col + 1);
            float v00 = c[mi][ni][0] + b0v, v01 = c[mi][ni][1] + b1v;
            float v10 = c[mi][ni][2] + b0v, v11 = c[mi][ni][3] + b1v;
            if (SPLIT) {
                int hh = col >> 6, hd = col & 63;
                int bi0 = r0 >> 11, s0 = r0 & 2047;
                int bi1 = r1 >> 11, s1 = r1 & 2047;
                size_t i0 = ((((size_t)bi0*NHEAD + hh)*SEQ) + s0)*HDIM + hd;
                size_t i1 = ((((size_t)bi1*NHEAD + hh)*SEQ) + s1)*HDIM + hd;
                __nv_bfloat162 h2, l2;
                h2.x = __float2bfloat16(v00); h2.y = __float2bfloat16(v01);
                l2.x = __float2bfloat16(v00 - __bfloat162float(h2.x));
                l2.y = __float2bfloat16(v01 - __bfloat162float(h2.y));
                *(__nv_bfloat162*)(Ch + i0) = h2;
                *(__nv_bfloat162*)(Cl + i0) = l2;
                h2.x = __float2bfloat16(v10); h2.y = __float2bfloat16(v11);
                l2.x = __float2bfloat16(v10 - __bfloat162float(h2.x));
                l2.y = __float2bfloat16(v11 - __bfloat162float(h2.y));
                *(__nv_bfloat162*)(Ch + i1) = h2;
                *(__nv_bfloat162*)(Cl + i1) = l2;
            } else {
                float2 v0 = {v00, v01}, v1 = {v10, v11};
                *(float2*)&Cf[(size_t)r0*DMODEL + col] = v0;
                *(float2*)&Cf[(size_t)r1*DMODEL + col] = v1;
            }
        }
    }
}

// ---------------- Flash attention (bf16x3, 2-stage ring, P-in-regs) ---------
// grid (SEQ/64, B*H), 128 threads (4 warps). Warp w owns query rows [w*16,+16).
// K/V smem per stage: {Kh,Kl,Vh,Vl} x 64 rows x 128B, swizzled. 2 stages = 64KB
// -> 3 CTAs/SM. Q staged through stage 1 in prologue; P stays in registers.
// ldmatrix.x4 fetches two k-chunks (K) / two hd-chunks (V) per instruction.
#define ASTG 32768
#define KM_OFF (2*ASTG)
#define ATTN_SMEM (KM_OFF + 2*64*4)

__global__ __launch_bounds__(128, 3) void attn_cp_kernel(
    const __nv_bfloat16* __restrict__ qhh, const __nv_bfloat16* __restrict__ qhl,
    const __nv_bfloat16* __restrict__ khh, const __nv_bfloat16* __restrict__ khl,
    const __nv_bfloat16* __restrict__ vhh, const __nv_bfloat16* __restrict__ vhl,
    __nv_bfloat16* __restrict__ obh, __nv_bfloat16* __restrict__ obl)
{
    extern __shared__ __align__(128) unsigned char smraw[];
    float* kmf = (float*)(smraw + KM_OFF);

    int t = threadIdx.x, lane = t & 31, w = t >> 5;
    int g = lane >> 2, cq = (lane & 3) * 2;
    int qt = blockIdx.x, bh = blockIdx.y;
    int b = bh >> 4, h = bh & 15;
    int q0 = qt * 64;
    size_t bhoff = (size_t)bh * SEQ * HDIM;
    const __nv_bfloat16* qbh = qhh + bhoff + (size_t)q0 * HDIM;
    const __nv_bfloat16* qbl = qhl + bhoff + (size_t)q0 * HDIM;
    const unsigned char* mb = g_mask + b * SEQ;

    uint32_t sbse = (uint32_t)__cvta_generic_to_shared(smraw);
    uint32_t x = (uint32_t)((lane & 7) << 4);

    int row = t >> 1, half = t & 1;
    uint32_t rxor = (uint32_t)((row & 7) << 4);
    const __nv_bfloat16* kvsrc[4] = {
        khh + bhoff + (size_t)row * HDIM + half * 32,
        khl + bhoff + (size_t)row * HDIM + half * 32,
        vhh + bhoff + (size_t)row * HDIM + half * 32,
        vhl + bhoff + (size_t)row * HDIM + half * 32 };

    auto issueKV = [&](int it2) {
        int st = it2 & 1;
        uint32_t base = sbse + st * ASTG + row * 128;
        size_t koff = (size_t)it2 * 64 * HDIM;
        #pragma unroll
        for (int rgn = 0; rgn < 4; ++rgn) {
            const __nv_bfloat16* src = kvsrc[rgn] + koff;
            uint32_t db = base + rgn * 8192;
            #pragma unroll
            for (int j = 0; j < 4; ++j) {
                uint32_t c = (uint32_t)(half * 64 + j * 16) ^ rxor;
                CP16(db + c, src + j * 8);
            }
        }
        if (t < 64) kmf[st*64 + t] = mb[it2*64 + t] ? 0.0f : NEG_INF;
    };

    issueKV(0); CP_COMMIT();

    // stage Q through stage-1 buffer (Qh at +0, Ql at +8192)
    {
        uint32_t qdst = sbse + ASTG + row * 128;
        const uint4* gqh = (const uint4*)(qbh + row * HDIM + half * 32);
        const uint4* gql = (const uint4*)(qbl + row * HDIM + half * 32);
        #pragma unroll
        for (int j = 0; j < 4; ++j) {
            uint32_t c = (uint32_t)(half * 64 + j * 16) ^ rxor;
            asm volatile("st.shared.v4.b32 [%0], {%1,%2,%3,%4};" ::
                "r"(qdst + c), "r"(gqh[j].x), "r"(gqh[j].y), "r"(gqh[j].z), "r"(gqh[j].w));
            asm volatile("st.shared.v4.b32 [%0], {%1,%2,%3,%4};" ::
                "r"(qdst + 8192 + c), "r"(gql[j].x), "r"(gql[j].y), "r"(gql[j].z), "r"(gql[j].w));
        }
    }
    __syncthreads();
    uint32_t qfh[4][4], qfl[4][4];
    {
        uint32_t qrow = (uint32_t)(w*16 + (lane & 15));
        uint32_t qc = (uint32_t)((lane >> 4) << 4);
        #pragma unroll
        for (int kt = 0; kt < 4; ++kt) {
            uint32_t c = ((uint32_t)(kt*32) + qc) ^ x;
            uint32_t addr = sbse + ASTG + qrow * 128 + c;
            ldm_x4(qfh[kt], addr);
            ldm_x4(qfl[kt], addr + 8192);
        }
    }
    __syncthreads();            // all warps have Q frags; stage 1 reusable
    issueKV(1); CP_COMMIT();

    float oc[8][4] = {};
    float m0r = NEG_INF, m1r = NEG_INF, l0r = 0.f, l1r = 0.f;
    uint32_t krow = (uint32_t)(lane & 7);
    uint32_t kq16 = (uint32_t)((lane >> 3) << 4);   // 0,16,32,48 per lane octet
    uint32_t vlr = (uint32_t)(lane & 15);
    uint32_t vsel = (uint32_t)((lane >> 4) << 4);   // 0 or 16: nt vs nt+1 col

    const int NT = SEQ / 64;   // 32
    for (int it = 0; it < NT; ++it) {
        if (it + 1 < NT) { CP_WAIT(1); } else { CP_WAIT(0); }
        __syncthreads();   // stage it&1 visible to all warps

        uint32_t stage = sbse + (uint32_t)(it & 1) * ASTG;
        const uint32_t KhB = stage, KlB = stage + 8192;
        const uint32_t VhB = stage + 16384, VlB = stage + 24576;
        const float* km = kmf + (it & 1) * 64;

        // S = Q K^T  (16 rows x 64 keys per warp); x4 loads 2 k-chunks at once
        float sc[8][4] = {};
        #pragma unroll
        for (int nt = 0; nt < 8; ++nt) {
            uint32_t rbase = ((uint32_t)(nt*8) + krow) * 128;
            #pragma unroll
            for (int ktp = 0; ktp < 2; ++ktp) {
                uint32_t c = ((uint32_t)(ktp*64) + kq16) ^ x;
                uint32_t kh4[4], kl4[4];
                ldm_x4(kh4, KhB + rbase + c);
                ldm_x4(kl4, KlB + rbase + c);
                mma16816(sc[nt], qfh[2*ktp],   kh4);
                mma16816(sc[nt], qfh[2*ktp],   kl4);
                mma16816(sc[nt], qfl[2*ktp],   kh4);
                mma16816(sc[nt], qfh[2*ktp+1], kh4 + 2);
                mma16816(sc[nt], qfh[2*ktp+1], kl4 + 2);
                mma16816(sc[nt], qfl[2*ktp+1], kh4 + 2);
            }
        }

        // online softmax (rows g and g+8 of warp strip)
        float r0m = NEG_INF, r1m = NEG_INF;
        #pragma unroll
        for (int nt = 0; nt < 8; ++nt) {
            float a0 = km[nt*8 + cq], a1 = km[nt*8 + cq + 1];
            sc[nt][0] = sc[nt][0]*0.125f + a0;
            sc[nt][1] = sc[nt][1]*0.125f + a1;
            sc[nt][2] = sc[nt][2]*0.125f + a0;
            sc[nt][3] = sc[nt][3]*0.125f + a1;
            r0m = fmaxf(r0m, fmaxf(sc[nt][0], sc[nt][1]));
            r1m = fmaxf(r1m, fmaxf(sc[nt][2], sc[nt][3]));
        }
        r0m = fmaxf(r0m, __shfl_xor_sync(0xffffffffu, r0m, 1));
        r0m = fmaxf(r0m, __shfl_xor_sync(0xffffffffu, r0m, 2));
        r1m = fmaxf(r1m, __shfl_xor_sync(0xffffffffu, r1m, 1));
        r1m = fmaxf(r1m, __shfl_xor_sync(0xffffffffu, r1m, 2));
        float mn0 = fmaxf(m0r, r0m), mn1 = fmaxf(m1r, r1m);
        float ms0 = (mn0 == NEG_INF) ? 0.0f : mn0;
        float ms1 = (mn1 == NEG_INF) ? 0.0f : mn1;
        float al0 = __expf(m0r - ms0), al1 = __expf(m1r - ms1);
        m0r = mn0; m1r = mn1;

        // exp + pack P directly into PV A-fragment registers
        uint32_t ph[8], ph2[8], pl[8], pl2[8];
        float rs0 = 0.f, rs1 = 0.f;
        #pragma unroll
        for (int nt = 0; nt < 8; ++nt) {
            float p0 = __expf(sc[nt][0] - ms0), p1 = __expf(sc[nt][1] - ms0);
            float p2 = __expf(sc[nt][2] - ms1), p3 = __expf(sc[nt][3] - ms1);
            rs0 += p0 + p1; rs1 += p2 + p3;
            __nv_bfloat162 hv0, hv1, lv0, lv1;
            hv0.x = __float2bfloat16(p0); hv0.y = __float2bfloat16(p1);
            hv1.x = __float2bfloat16(p2); hv1.y = __float2bfloat16(p3);
            lv0.x = __float2bfloat16(p0 - __bfloat162float(hv0.x));
            lv0.y = __float2bfloat16(p1 - __bfloat162float(hv0.y));
            lv1.x = __float2bfloat16(p2 - __bfloat162float(hv1.x));
            lv1.y = __float2bfloat16(p3 - __bfloat162float(hv1.y));
            ph[nt]  = *(uint32_t*)&hv0;
            ph2[nt] = *(uint32_t*)&hv1;
            pl[nt]  = *(uint32_t*)&lv0;
            pl2[nt] = *(uint32_t*)&lv1;
        }
        rs0 += __shfl_xor_sync(0xffffffffu, rs0, 1);
        rs0 += __shfl_xor_sync(0xffffffffu, rs0, 2);
        rs1 += __shfl_xor_sync(0xffffffffu, rs1, 1);
        rs1 += __shfl_xor_sync(0xffffffffu, rs1, 2);
        l0r = l0r * al0 + rs0;
        l1r = l1r * al1 + rs1;
        #pragma unroll
        for (int nt = 0; nt < 8; ++nt) {
            oc[nt][0] *= al0; oc[nt][1] *= al0;
            oc[nt][2] *= al1; oc[nt][3] *= al1;
        }

        // O += P V ; x4.trans loads 2 hd-chunks at once
        #pragma unroll
        for (int kt = 0; kt < 4; ++kt) {
            uint32_t pa[4]  = {ph[2*kt],  ph2[2*kt],  ph[2*kt+1],  ph2[2*kt+1]};
            uint32_t pla[4] = {pl[2*kt],  pl2[2*kt],  pl[2*kt+1],  pl2[2*kt+1]};
            uint32_t vr = ((uint32_t)(kt*16) + vlr) * 128;
            #pragma unroll
            for (int ntp = 0; ntp < 4; ++ntp) {
                uint32_t c = ((uint32_t)(ntp*32) + vsel) ^ x;
                uint32_t vh4[4], vl4[4];
                ldm_x4t(vh4, VhB + vr + c);
                ldm_x4t(vl4, VlB + vr + c);
                mma16816(oc[2*ntp],   pa,  vh4);
                mma16816(oc[2*ntp],   pa,  vl4);
                mma16816(oc[2*ntp],   pla, vh4);
                mma16816(oc[2*ntp+1], pa,  vh4 + 2);
                mma16816(oc[2*ntp+1], pa,  vl4 + 2);
                mma16816(oc[2*ntp+1], pla, vh4 + 2);
            }
        }
        __syncthreads();   // all warps done with stage it&1
        if (it + 2 < NT) { issueKV(it + 2); CP_COMMIT(); }
    }

    // epilogue: normalize, zero masked query rows, write (b,s,d) as bf16 hi/lo
    int r0 = w*16 + g, r1 = r0 + 8;
    float inv0 = (mb[q0 + r0] && l0r > 0.f) ? 1.0f / l0r : 0.0f;
    float inv1 = (mb[q0 + r1] && l1r > 0.f) ? 1.0f / l1r : 0.0f;
    size_t base0 = ((size_t)b*SEQ + q0 + r0)*DMODEL + h*HDIM;
    size_t base1 = ((size_t)b*SEQ + q0 + r1)*DMODEL + h*HDIM;
    #pragma unroll
    for (int nt = 0; nt < 8; ++nt) {
        float v00 = oc[nt][0]*inv0, v01 = oc[nt][1]*inv0;
        float v10 = oc[nt][2]*inv1, v11 = oc[nt][3]*inv1;
        __nv_bfloat162 h0, l0, h1, l1;
        h0.x = __float2bfloat16(v00); h0.y = __float2bfloat16(v01);
        l0.x = __float2bfloat16(v00 - __bfloat162float(h0.x));
        l0.y = __float2bfloat16(v01 - __bfloat162float(h0.y));
        h1.x = __float2bfloat16(v10); h1.y = __float2bfloat16(v11);
        l1.x = __float2bfloat16(v10 - __bfloat162float(h1.x));
        l1.y = __float2bfloat16(v11 - __bfloat162float(h1.y));
        *(__nv_bfloat162*)(obh + base0 + nt*8 + cq) = h0;
        *(__nv_bfloat162*)(obl + base0 + nt*8 + cq) = l0;
        *(__nv_bfloat162*)(obh + base1 + nt*8 + cq) = h1;
        *(__nv_bfloat162*)(obl + base1 + nt*8 + cq) = l1;
    }
}

// ---------------- launch ----------------------------------------------------
extern "C" void kernel_launch(void* const* d_in, const int* in_sizes, int n_in,
                              void* d_out, int out_size) {
    const float* q    = (const float*)d_in[0];
    const unsigned char* mask = (const unsigned char*)d_in[1];
    const float* Wq   = (const float*)d_in[2];
    const float* bq   = (const float*)d_in[3];
    const float* Wk   = (const float*)d_in[4];
    const float* bk   = (const float*)d_in[5];
    const float* Wv   = (const float*)d_in[6];
    const float* bv   = (const float*)d_in[7];
    const float* Wo   = (const float*)d_in[8];
    const float* bo   = (const float*)d_in[9];
    float* out = (float*)d_out;

    __nv_bfloat16 *ah, *al, *wh, *wl, *qhh, *qhl, *khh, *khl, *vhh, *vhl, *oh, *ol;
    cudaGetSymbolAddress((void**)&ah,  g_ah);
    cudaGetSymbolAddress((void**)&al,  g_al);
    cudaGetSymbolAddress((void**)&wh,  g_wh);
    cudaGetSymbolAddress((void**)&wl,  g_wl);
    cudaGetSymbolAddress((void**)&qhh, g_qhh);
    cudaGetSymbolAddress((void**)&qhl, g_qhl);
    cudaGetSymbolAddress((void**)&khh, g_khh);
    cudaGetSymbolAddress((void**)&khl, g_khl);
    cudaGetSymbolAddress((void**)&vhh, g_vhh);
    cudaGetSymbolAddress((void**)&vhl, g_vhl);
    cudaGetSymbolAddress((void**)&oh,  g_oh);
    cudaGetSymbolAddress((void**)&ol,  g_ol);

    detect_mask_kernel<<<1, 256>>>(mask);
    convert_mask_kernel<<<(BATCH*SEQ + 255) / 256, 256>>>(mask);

    split_kernel<<<NELEM / 1024, 256>>>(q, ah, al, NELEM);
    split_w_kernel<<<dim3(1024, 1, 4), 256>>>(Wq, Wk, Wv, Wo, wh, wl);

    const int gemm_smem = 3 * GSTAGE;   // 98304 B
    static bool attr_done = false;
    if (!attr_done) {
        cudaFuncSetAttribute(gemm_cp_kernel<true>,
                             cudaFuncAttributeMaxDynamicSharedMemorySize, gemm_smem);
        cudaFuncSetAttribute(gemm_cp_kernel<false>,
                             cudaFuncAttributeMaxDynamicSharedMemorySize, gemm_smem);
        cudaFuncSetAttribute(attn_cp_kernel,
                             cudaFuncAttributeMaxDynamicSharedMemorySize, ATTN_SMEM);
        attr_done = true;
    }

    // fused QKV projections
    gemm_cp_kernel<true><<<dim3(8, 64, 3), 256, gemm_smem>>>(
        ah, al, wh, wl, 0, bq, bk, bv,
        qhh, qhl, khh, khl, vhh, vhl, nullptr);

    attn_cp_kernel<<<dim3(SEQ / 64, BATCH * NHEAD), 128, ATTN_SMEM>>>(
        qhh, qhl, khh, khl, vhh, vhl, oh, ol);

    // output projection -> fp32 out
    gemm_cp_kernel<false><<<dim3(8, 64, 1), 256, gemm_smem>>>(
        oh, ol, wh, wl, 3, bo, bo, bo,
        nullptr, nullptr, nullptr, nullptr, nullptr, nullptr, out);
}

// round 8
// speedup vs baseline: 1.5968x; 1.5968x over previous
#include <cuda_runtime.h>
#include <cuda_fp16.h>
#include <cstdint>

// Problem constants
#define BATCH 4
#define SEQ   2048
#define DMODEL 1024
#define NHEAD 16
#define HDIM  64
#define MROWS (BATCH*SEQ)         // 8192

#define NEG_INF __int_as_float(0xff800000)

// ---------------- scratch (device globals; no allocation allowed) ----------
#define NELEM (8192*1024)
__device__ __half g_ah[NELEM];                            // input x, fp16 hi only
__device__ __half g_wh[4*1024*1024], g_wl[4*1024*1024];   // Wq,Wk,Wv,Wo hi/lo
__device__ __half g_qhh[NELEM];                           // Q heads hi only
__device__ __half g_khh[NELEM], g_khl[NELEM];             // K heads hi/lo
__device__ __half g_vhh[NELEM], g_vhl[NELEM];             // V heads hi/lo
__device__ __half g_oh[NELEM];                            // attn out hi only
__device__ unsigned char g_mask[BATCH*SEQ];
__device__ int g_mode;

// ---------------- mask dtype detection + canonicalization ------------------
__global__ void detect_mask_kernel(const unsigned char* __restrict__ p) {
    __shared__ int s1, s3;
    if (threadIdx.x == 0) { s1 = 0; s3 = 0; }
    __syncthreads();
    int l1 = 0, l3 = 0;
    for (int i = threadIdx.x; i < BATCH*SEQ; i += blockDim.x) {
        unsigned char v = p[i];
        int m = i & 3;
        if (m == 1 && v) l1 = 1;
        if (m == 3 && v) l3 = 1;
    }
    if (l1) atomicOr(&s1, 1);
    if (l3) atomicOr(&s3, 1);
    __syncthreads();
    if (threadIdx.x == 0) g_mode = s1 ? 0 : (s3 ? 1 : 2);  // 0=u8, 1=f32, 2=i32
}

__global__ void convert_mask_kernel(const unsigned char* __restrict__ p) {
    int i = blockIdx.x * blockDim.x + threadIdx.x;
    if (i >= BATCH*SEQ) return;
    int mode = g_mode;
    unsigned char r;
    if (mode == 0)      r = (p[i] != 0);
    else if (mode == 1) r = (((const float*)p)[i] != 0.0f);
    else                r = (((const int*)p)[i] != 0);
    g_mask[i] = r;
}

// ---------------- fp32 -> fp16 conversion kernels ---------------------------
__global__ void tohalf_kernel(const float* __restrict__ src,
                              __half* __restrict__ hi, int n) {
    int i = (blockIdx.x * blockDim.x + threadIdx.x) * 4;
    if (i >= n) return;
    float4 v = *(const float4*)(src + i);
    __half2 a = __floats2half2_rn(v.x, v.y);
    __half2 b = __floats2half2_rn(v.z, v.w);
    *(__half2*)(hi + i)     = a;
    *(__half2*)(hi + i + 2) = b;
}

__global__ void split_w_kernel(const float* __restrict__ w0, const float* __restrict__ w1,
                               const float* __restrict__ w2, const float* __restrict__ w3,
                               __half* __restrict__ hi, __half* __restrict__ lo) {
    int z = blockIdx.z;
    const float* src = (z==0)?w0:(z==1)?w1:(z==2)?w2:w3;
    size_t off = (size_t)z * 1024 * 1024;
    int i = (blockIdx.x * blockDim.x + threadIdx.x) * 4;
    float4 v = *(const float4*)(src + i);
    float f[4] = {v.x, v.y, v.z, v.w};
    __half h[4], l[4];
    #pragma unroll
    for (int j = 0; j < 4; ++j) {
        h[j] = __float2half_rn(f[j]);
        l[j] = __float2half_rn(f[j] - __half2float(h[j]));
    }
    *(__half2*)(hi + off + i)     = __halves2half2(h[0], h[1]);
    *(__half2*)(hi + off + i + 2) = __halves2half2(h[2], h[3]);
    *(__half2*)(lo + off + i)     = __halves2half2(l[0], l[1]);
    *(__half2*)(lo + off + i + 2) = __halves2half2(l[2], l[3]);
}

// ---------------- mma / ldmatrix / cp.async primitives ----------------------
__device__ __forceinline__ void mma16816(float* c, const uint32_t* a, const uint32_t* b) {
    asm volatile(
        "mma.sync.aligned.m16n8k16.row.col.f32.f16.f16.f32 "
        "{%0,%1,%2,%3}, {%4,%5,%6,%7}, {%8,%9}, {%0,%1,%2,%3};"
        : "+f"(c[0]), "+f"(c[1]), "+f"(c[2]), "+f"(c[3])
        : "r"(a[0]), "r"(a[1]), "r"(a[2]), "r"(a[3]), "r"(b[0]), "r"(b[1]));
}
__device__ __forceinline__ void ldm_x4(uint32_t* r, uint32_t addr) {
    asm volatile("ldmatrix.sync.aligned.m8n8.x4.shared.b16 {%0,%1,%2,%3}, [%4];"
                 : "=r"(r[0]), "=r"(r[1]), "=r"(r[2]), "=r"(r[3]) : "r"(addr));
}
__device__ __forceinline__ void ldm_x4t(uint32_t* r, uint32_t addr) {
    asm volatile("ldmatrix.sync.aligned.m8n8.x4.trans.shared.b16 {%0,%1,%2,%3}, [%4];"
                 : "=r"(r[0]), "=r"(r[1]), "=r"(r[2]), "=r"(r[3]) : "r"(addr));
}
#define CP16(dst, src) \
    asm volatile("cp.async.cg.shared.global [%0], [%1], 16;" :: "r"(dst), "l"(src))
#define CP_COMMIT() asm volatile("cp.async.commit_group;" ::: "memory")
#define CP_WAIT(n)  asm volatile("cp.async.wait_group %0;" :: "n"(n) : "memory")

// ---------------- GEMM: C = A @ W^T + bias (fp16x2, cp.async 3-stage) -------
// A: fp16 hi only [M,1024]; W: fp16 hi/lo [N,1024]. BM=BN=128, BK=64.
// smem stage 48KB: A 16KB (128 rows x 128B = 64 fp16), Bh 16KB, Bl 16KB.
// swizzle: byte chunk bits [6:4] ^= row&7. 8 warps (2x4), warp tile 64x32.
// C = Ah*Bh + Ah*Bl  (2 MMAs per tile).
#define GSTG 49152
#define GNIT 16

template <bool SPLIT>
__global__ __launch_bounds__(256, 1) void gemm_cp_kernel(
    const __half* __restrict__ Ag,
    const __half* __restrict__ Whb, const __half* __restrict__ Wlb, int woff,
    const float* b0, const float* b1, const float* b2,
    __half* C0h, __half* C0l,
    __half* C1h, __half* C1l,
    __half* C2h, __half* C2l,
    float* Cf)
{
    int z = blockIdx.z;
    const __half* Wh = Whb + (size_t)(woff + z) * 1024 * 1024;
    const __half* Wl = Wlb + (size_t)(woff + z) * 1024 * 1024;
    const float* bias = (z == 0) ? b0 : (z == 1) ? b1 : b2;
    __half* Ch = (z == 0) ? C0h : (z == 1) ? C1h : C2h;
    __half* Cl = (z == 0) ? C0l : (z == 1) ? C1l : C2l;

    extern __shared__ __align__(128) unsigned char smraw[];
    uint32_t sb = (uint32_t)__cvta_generic_to_shared(smraw);

    int t = threadIdx.x, lane = t & 31, warp = t >> 5;
    int wm = warp >> 2, wn = warp & 3;
    int m0 = blockIdx.y * 128, n0 = blockIdx.x * 128;

    int row = t >> 1, half = t & 1;
    const __half* srcA  = Ag + (size_t)(m0 + row) * 1024 + half * 32;
    const __half* srcBh = Wh + (size_t)(n0 + row) * 1024 + half * 32;
    const __half* srcBl = Wl + (size_t)(n0 + row) * 1024 + half * 32;
    uint32_t rxor = (uint32_t)((row & 7) << 4);
    uint32_t dA = sb + row * 128;

    auto issue = [&](int ch) {
        uint32_t base = dA + (uint32_t)(ch % 3) * GSTG;
        const __half* sa = srcA  + ch * 64;
        const __half* sh = srcBh + ch * 64;
        const __half* sl = srcBl + ch * 64;
        #pragma unroll
        for (int j = 0; j < 4; ++j) {
            uint32_t c = (uint32_t)(half * 64 + j * 16) ^ rxor;
            CP16(base + c,         sa + j * 8);
            CP16(base + 16384 + c, sh + j * 8);
            CP16(base + 32768 + c, sl + j * 8);
        }
    };

    float c[4][4][4] = {};
    uint32_t x = (uint32_t)((lane & 7) << 4);
    uint32_t arowb = (uint32_t)((wm * 64 + (lane & 15)) * 128);
    uint32_t acol = (uint32_t)((lane >> 4) << 4);
    uint32_t browb = (uint32_t)((wn * 32 + (lane & 7) + ((lane >> 4) << 3)) * 128);
    uint32_t bcol = (uint32_t)(((lane >> 3) & 1) << 4);

    issue(0); CP_COMMIT();
    issue(1); CP_COMMIT();

    for (int it = 0; it < GNIT; ++it) {
        if (it + 1 < GNIT) { CP_WAIT(1); } else { CP_WAIT(0); }
        __syncthreads();
        if (it + 2 < GNIT) { issue(it + 2); CP_COMMIT(); }

        uint32_t Abase  = sb + (uint32_t)(it % 3) * GSTG;
        uint32_t Bhbase = Abase + 16384;
        uint32_t Blbase = Abase + 32768;
        #pragma unroll
        for (int kt = 0; kt < 4; ++kt) {
            uint32_t ac = ((uint32_t)(kt * 32) + acol) ^ x;
            uint32_t af[4][4];
            #pragma unroll
            for (int mi = 0; mi < 4; ++mi)
                ldm_x4(af[mi], Abase + arowb + mi * 16 * 128 + ac);
            uint32_t bc = ((uint32_t)(kt * 32) + bcol) ^ x;
            #pragma unroll
            for (int nip = 0; nip < 2; ++nip) {
                uint32_t baddr = browb + nip * 16 * 128 + bc;
                uint32_t bh4[4], bl4[4];
                ldm_x4(bh4, Bhbase + baddr);
                ldm_x4(bl4, Blbase + baddr);
                #pragma unroll
                for (int mi = 0; mi < 4; ++mi) {
                    mma16816(c[mi][2*nip],   af[mi], bh4);
                    mma16816(c[mi][2*nip],   af[mi], bl4);
                    mma16816(c[mi][2*nip+1], af[mi], bh4 + 2);
                    mma16816(c[mi][2*nip+1], af[mi], bl4 + 2);
                }
            }
        }
    }

    // epilogue
    int g = lane >> 2, cq = (lane & 3) * 2;
    #pragma unroll
    for (int mi = 0; mi < 4; ++mi) {
        int r0 = m0 + wm*64 + mi*16 + g;
        int r1 = r0 + 8;
        #pragma unroll
        for (int ni = 0; ni < 4; ++ni) {
            int col = n0 + wn*32 + ni*8 + cq;
            float b0v = __ldg(bias + col), b1v = __ldg(bias + col + 1);
            float v00 = c[mi][ni][0] + b0v, v01 = c[mi][ni][1] + b1v;
            float v10 = c[mi][ni][2] + b0v, v11 = c[mi][ni][3] + b1v;
            if (SPLIT) {
                int hh = col >> 6, hd = col & 63;
                int bi0 = r0 >> 11, s0 = r0 & 2047;
                int bi1 = r1 >> 11, s1 = r1 & 2047;
                size_t i0 = ((((size_t)bi0*NHEAD + hh)*SEQ) + s0)*HDIM + hd;
                size_t i1 = ((((size_t)bi1*NHEAD + hh)*SEQ) + s1)*HDIM + hd;
                __half2 h0 = __floats2half2_rn(v00, v01);
                __half2 h1 = __floats2half2_rn(v10, v11);
                *(__half2*)(Ch + i0) = h0;
                *(__half2*)(Ch + i1) = h1;
                if (Cl) {
                    __half2 l0 = __floats2half2_rn(v00 - __half2float(__low2half(h0)),
                                                   v01 - __half2float(__high2half(h0)));
                    __half2 l1 = __floats2half2_rn(v10 - __half2float(__low2half(h1)),
                                                   v11 - __half2float(__high2half(h1)));
                    *(__half2*)(Cl + i0) = l0;
                    *(__half2*)(Cl + i1) = l1;
                }
            } else {
                float2 v0 = {v00, v01}, v1 = {v10, v11};
                *(float2*)&Cf[(size_t)r0*DMODEL + col] = v0;
                *(float2*)&Cf[(size_t)r1*DMODEL + col] = v1;
            }
        }
    }
}

// ---------------- Flash attention (fp16x2, 2-stage ring, P-in-regs) ---------
// grid (SEQ/64, B*H), 128 threads (4 warps). Warp w owns query rows [w*16,+16).
// K/V smem per stage: {Kh,Kl,Vh,Vl} x 64 rows x 128B, swizzled. 2 stages = 64KB.
// Q fp16 hi only (register-resident frags); P fp16 hi only, never touches smem.
// S = Qh*Kh + Qh*Kl ; O += Ph*Vh + Ph*Vl.
#define ASTG 32768
#define KM_OFF (2*ASTG)
#define ATTN_SMEM (KM_OFF + 2*64*4)

__global__ __launch_bounds__(128, 3) void attn_cp_kernel(
    const __half* __restrict__ qhh,
    const __half* __restrict__ khh, const __half* __restrict__ khl,
    const __half* __restrict__ vhh, const __half* __restrict__ vhl,
    __half* __restrict__ obh)
{
    extern __shared__ __align__(128) unsigned char smraw[];
    float* kmf = (float*)(smraw + KM_OFF);

    int t = threadIdx.x, lane = t & 31, w = t >> 5;
    int g = lane >> 2, cq = (lane & 3) * 2;
    int qt = blockIdx.x, bh = blockIdx.y;
    int b = bh >> 4, h = bh & 15;
    int q0 = qt * 64;
    size_t bhoff = (size_t)bh * SEQ * HDIM;
    const __half* qb = qhh + bhoff + (size_t)q0 * HDIM;
    const unsigned char* mb = g_mask + b * SEQ;

    uint32_t sbse = (uint32_t)__cvta_generic_to_shared(smraw);
    uint32_t x = (uint32_t)((lane & 7) << 4);

    int row = t >> 1, half = t & 1;
    uint32_t rxor = (uint32_t)((row & 7) << 4);
    const __half* kvsrc[4] = {
        khh + bhoff + (size_t)row * HDIM + half * 32,
        khl + bhoff + (size_t)row * HDIM + half * 32,
        vhh + bhoff + (size_t)row * HDIM + half * 32,
        vhl + bhoff + (size_t)row * HDIM + half * 32 };

    auto issueKV = [&](int it2) {
        int st = it2 & 1;
        uint32_t base = sbse + st * ASTG + row * 128;
        size_t koff = (size_t)it2 * 64 * HDIM;
        #pragma unroll
        for (int rgn = 0; rgn < 4; ++rgn) {
            const __half* src = kvsrc[rgn] + koff;
            uint32_t db = base + rgn * 8192;
            #pragma unroll
            for (int j = 0; j < 4; ++j) {
                uint32_t c = (uint32_t)(half * 64 + j * 16) ^ rxor;
                CP16(db + c, src + j * 8);
            }
        }
        if (t < 64) kmf[st*64 + t] = mb[it2*64 + t] ? 0.0f : NEG_INF;
    };

    issueKV(0); CP_COMMIT();

    // stage Q (hi) through stage-1 buffer
    {
        uint32_t qdst = sbse + ASTG + row * 128;
        const uint4* gq = (const uint4*)(qb + row * HDIM + half * 32);
        #pragma unroll
        for (int j = 0; j < 4; ++j) {
            uint32_t c = (uint32_t)(half * 64 + j * 16) ^ rxor;
            uint4 v = gq[j];
            asm volatile("st.shared.v4.b32 [%0], {%1,%2,%3,%4};" ::
                "r"(qdst + c), "r"(v.x), "r"(v.y), "r"(v.z), "r"(v.w));
        }
    }
    __syncthreads();
    uint32_t qf[4][4];
    {
        uint32_t qrow = (uint32_t)(w*16 + (lane & 15));
        uint32_t qc = (uint32_t)((lane >> 4) << 4);
        #pragma unroll
        for (int kt = 0; kt < 4; ++kt) {
            uint32_t c = ((uint32_t)(kt*32) + qc) ^ x;
            ldm_x4(qf[kt], sbse + ASTG + qrow * 128 + c);
        }
    }
    __syncthreads();            // all warps have Q frags; stage 1 reusable
    issueKV(1); CP_COMMIT();

    float oc[8][4] = {};
    float m0r = NEG_INF, m1r = NEG_INF, l0r = 0.f, l1r = 0.f;
    uint32_t krow = (uint32_t)(lane & 7);
    uint32_t kq16 = (uint32_t)((lane >> 3) << 4);   // 0,16,32,48 per lane octet
    uint32_t vlr = (uint32_t)(lane & 15);
    uint32_t vsel = (uint32_t)((lane >> 4) << 4);

    const int NT = SEQ / 64;   // 32
    for (int it = 0; it < NT; ++it) {
        if (it + 1 < NT) { CP_WAIT(1); } else { CP_WAIT(0); }
        __syncthreads();   // stage it&1 visible to all warps

        uint32_t stage = sbse + (uint32_t)(it & 1) * ASTG;
        const uint32_t KhB = stage, KlB = stage + 8192;
        const uint32_t VhB = stage + 16384, VlB = stage + 24576;
        const float* km = kmf + (it & 1) * 64;

        // S = Qh Kh^T + Qh Kl^T  (16 rows x 64 keys per warp)
        float sc[8][4] = {};
        #pragma unroll
        for (int nt = 0; nt < 8; ++nt) {
            uint32_t rbase = ((uint32_t)(nt*8) + krow) * 128;
            #pragma unroll
            for (int ktp = 0; ktp < 2; ++ktp) {
                uint32_t c = ((uint32_t)(ktp*64) + kq16) ^ x;
                uint32_t kh4[4], kl4[4];
                ldm_x4(kh4, KhB + rbase + c);
                ldm_x4(kl4, KlB + rbase + c);
                mma16816(sc[nt], qf[2*ktp],   kh4);
                mma16816(sc[nt], qf[2*ktp],   kl4);
                mma16816(sc[nt], qf[2*ktp+1], kh4 + 2);
                mma16816(sc[nt], qf[2*ktp+1], kl4 + 2);
            }
        }

        // online softmax (rows g and g+8 of warp strip)
        float r0m = NEG_INF, r1m = NEG_INF;
        #pragma unroll
        for (int nt = 0; nt < 8; ++nt) {
            float a0 = km[nt*8 + cq], a1 = km[nt*8 + cq + 1];
            sc[nt][0] = sc[nt][0]*0.125f + a0;
            sc[nt][1] = sc[nt][1]*0.125f + a1;
            sc[nt][2] = sc[nt][2]*0.125f + a0;
            sc[nt][3] = sc[nt][3]*0.125f + a1;
            r0m = fmaxf(r0m, fmaxf(sc[nt][0], sc[nt][1]));
            r1m = fmaxf(r1m, fmaxf(sc[nt][2], sc[nt][3]));
        }
        r0m = fmaxf(r0m, __shfl_xor_sync(0xffffffffu, r0m, 1));
        r0m = fmaxf(r0m, __shfl_xor_sync(0xffffffffu, r0m, 2));
        r1m = fmaxf(r1m, __shfl_xor_sync(0xffffffffu, r1m, 1));
        r1m = fmaxf(r1m, __shfl_xor_sync(0xffffffffu, r1m, 2));
        float mn0 = fmaxf(m0r, r0m), mn1 = fmaxf(m1r, r1m);
        float ms0 = (mn0 == NEG_INF) ? 0.0f : mn0;
        float ms1 = (mn1 == NEG_INF) ? 0.0f : mn1;
        float al0 = __expf(m0r - ms0), al1 = __expf(m1r - ms1);
        m0r = mn0; m1r = mn1;

        // exp + pack P (fp16 hi) directly into PV A-fragment registers
        uint32_t ph[8], ph2[8];
        float rs0 = 0.f, rs1 = 0.f;
        #pragma unroll
        for (int nt = 0; nt < 8; ++nt) {
            float p0 = __expf(sc[nt][0] - ms0), p1 = __expf(sc[nt][1] - ms0);
            float p2 = __expf(sc[nt][2] - ms1), p3 = __expf(sc[nt][3] - ms1);
            rs0 += p0 + p1; rs1 += p2 + p3;
            __half2 hv0 = __floats2half2_rn(p0, p1);
            __half2 hv1 = __floats2half2_rn(p2, p3);
            ph[nt]  = *(uint32_t*)&hv0;
            ph2[nt] = *(uint32_t*)&hv1;
        }
        rs0 += __shfl_xor_sync(0xffffffffu, rs0, 1);
        rs0 += __shfl_xor_sync(0xffffffffu, rs0, 2);
        rs1 += __shfl_xor_sync(0xffffffffu, rs1, 1);
        rs1 += __shfl_xor_sync(0xffffffffu, rs1, 2);
        l0r = l0r * al0 + rs0;
        l1r = l1r * al1 + rs1;
        #pragma unroll
        for (int nt = 0; nt < 8; ++nt) {
            oc[nt][0] *= al0; oc[nt][1] *= al0;
            oc[nt][2] *= al1; oc[nt][3] *= al1;
        }

        // O += Ph Vh + Ph Vl
        #pragma unroll
        for (int kt = 0; kt < 4; ++kt) {
            uint32_t pa[4] = {ph[2*kt], ph2[2*kt], ph[2*kt+1], ph2[2*kt+1]};
            uint32_t vr = ((uint32_t)(kt*16) + vlr) * 128;
            #pragma unroll
            for (int ntp = 0; ntp < 4; ++ntp) {
                uint32_t c = ((uint32_t)(ntp*32) + vsel) ^ x;
                uint32_t vh4[4], vl4[4];
                ldm_x4t(vh4, VhB + vr + c);
                ldm_x4t(vl4, VlB + vr + c);
                mma16816(oc[2*ntp],   pa, vh4);
                mma16816(oc[2*ntp],   pa, vl4);
                mma16816(oc[2*ntp+1], pa, vh4 + 2);
                mma16816(oc[2*ntp+1], pa, vl4 + 2);
            }
        }
        __syncthreads();   // all warps done with stage it&1
        if (it + 2 < NT) { issueKV(it + 2); CP_COMMIT(); }
    }

    // epilogue: normalize, zero masked query rows, write (b,s,d) as fp16 hi
    int r0 = w*16 + g, r1 = r0 + 8;
    float inv0 = (mb[q0 + r0] && l0r > 0.f) ? 1.0f / l0r : 0.0f;
    float inv1 = (mb[q0 + r1] && l1r > 0.f) ? 1.0f / l1r : 0.0f;
    size_t base0 = ((size_t)b*SEQ + q0 + r0)*DMODEL + h*HDIM;
    size_t base1 = ((size_t)b*SEQ + q0 + r1)*DMODEL + h*HDIM;
    #pragma unroll
    for (int nt = 0; nt < 8; ++nt) {
        __half2 h0 = __floats2half2_rn(oc[nt][0]*inv0, oc[nt][1]*inv0);
        __half2 h1 = __floats2half2_rn(oc[nt][2]*inv1, oc[nt][3]*inv1);
        *(__half2*)(obh + base0 + nt*8 + cq) = h0;
        *(__half2*)(obh + base1 + nt*8 + cq) = h1;
    }
}

// ---------------- launch ----------------------------------------------------
extern "C" void kernel_launch(void* const* d_in, const int* in_sizes, int n_in,
                              void* d_out, int out_size) {
    const float* q    = (const float*)d_in[0];
    const unsigned char* mask = (const unsigned char*)d_in[1];
    const float* Wq   = (const float*)d_in[2];
    const float* bq   = (const float*)d_in[3];
    const float* Wk   = (const float*)d_in[4];
    const float* bk   = (const float*)d_in[5];
    const float* Wv   = (const float*)d_in[6];
    const float* bv   = (const float*)d_in[7];
    const float* Wo   = (const float*)d_in[8];
    const float* bo   = (const float*)d_in[9];
    float* out = (float*)d_out;

    __half *ah, *wh, *wl, *qhh, *khh, *khl, *vhh, *vhl, *oh;
    cudaGetSymbolAddress((void**)&ah,  g_ah);
    cudaGetSymbolAddress((void**)&wh,  g_wh);
    cudaGetSymbolAddress((void**)&wl,  g_wl);
    cudaGetSymbolAddress((void**)&qhh, g_qhh);
    cudaGetSymbolAddress((void**)&khh, g_khh);
    cudaGetSymbolAddress((void**)&khl, g_khl);
    cudaGetSymbolAddress((void**)&vhh, g_vhh);
    cudaGetSymbolAddress((void**)&vhl, g_vhl);
    cudaGetSymbolAddress((void**)&oh,  g_oh);

    detect_mask_kernel<<<1, 256>>>(mask);
    convert_mask_kernel<<<(BATCH*SEQ + 255) / 256, 256>>>(mask);

    tohalf_kernel<<<NELEM / 1024, 256>>>(q, ah, NELEM);
    split_w_kernel<<<dim3(1024, 1, 4), 256>>>(Wq, Wk, Wv, Wo, wh, wl);

    const int gemm_smem = 3 * GSTG;   // 147456 B
    static bool attr_done = false;
    if (!attr_done) {
        cudaFuncSetAttribute(gemm_cp_kernel<true>,
                             cudaFuncAttributeMaxDynamicSharedMemorySize, gemm_smem);
        cudaFuncSetAttribute(gemm_cp_kernel<false>,
                             cudaFuncAttributeMaxDynamicSharedMemorySize, gemm_smem);
        cudaFuncSetAttribute(attn_cp_kernel,
                             cudaFuncAttributeMaxDynamicSharedMemorySize, ATTN_SMEM);
        attr_done = true;
    }

    // fused QKV projections (Q -> hi only; K,V -> hi+lo)
    gemm_cp_kernel<true><<<dim3(8, 64, 3), 256, gemm_smem>>>(
        ah, wh, wl, 0, bq, bk, bv,
        qhh, nullptr, khh, khl, vhh, vhl, nullptr);

    attn_cp_kernel<<<dim3(SEQ / 64, BATCH * NHEAD), 128, ATTN_SMEM>>>(
        qhh, khh, khl, vhh, vhl, oh);

    // output projection -> fp32 out
    gemm_cp_kernel<false><<<dim3(8, 64, 1), 256, gemm_smem>>>(
        oh, wh, wl, 3, bo, bo, bo,
        nullptr, nullptr, nullptr, nullptr, nullptr, nullptr, out);
}

// round 9
// speedup vs baseline: 1.7412x; 1.0904x over previous
#include <cuda_runtime.h>
#include <cuda_fp16.h>
#include <cstdint>

// Problem constants
#define BATCH 4
#define SEQ   2048
#define DMODEL 1024
#define NHEAD 16
#define HDIM  64
#define MROWS (BATCH*SEQ)         // 8192

#define NEG_INF __int_as_float(0xff800000)

// ---------------- scratch (device globals; no allocation allowed) ----------
#define NELEM (8192*1024)
__device__ __half g_ah[NELEM];                            // input x, fp16 hi only
__device__ __half g_wh[4*1024*1024], g_wl[4*1024*1024];   // Wq,Wk,Wv,Wo hi/lo
__device__ __half g_qhh[NELEM];                           // Q heads hi only
__device__ __half g_khh[NELEM], g_khl[NELEM];             // K heads hi/lo
__device__ __half g_vhh[NELEM], g_vhl[NELEM];             // V heads hi/lo
__device__ __half g_oh[NELEM];                            // attn out hi only
__device__ unsigned char g_mask[BATCH*SEQ];
__device__ int g_mode;

// ---------------- mask dtype detection + canonicalization ------------------
__global__ void detect_mask_kernel(const unsigned char* __restrict__ p) {
    __shared__ int s1, s3;
    if (threadIdx.x == 0) { s1 = 0; s3 = 0; }
    __syncthreads();
    int l1 = 0, l3 = 0;
    for (int i = threadIdx.x; i < BATCH*SEQ; i += blockDim.x) {
        unsigned char v = p[i];
        int m = i & 3;
        if (m == 1 && v) l1 = 1;
        if (m == 3 && v) l3 = 1;
    }
    if (l1) atomicOr(&s1, 1);
    if (l3) atomicOr(&s3, 1);
    __syncthreads();
    if (threadIdx.x == 0) g_mode = s1 ? 0 : (s3 ? 1 : 2);  // 0=u8, 1=f32, 2=i32
}

__global__ void convert_mask_kernel(const unsigned char* __restrict__ p) {
    int i = blockIdx.x * blockDim.x + threadIdx.x;
    if (i >= BATCH*SEQ) return;
    int mode = g_mode;
    unsigned char r;
    if (mode == 0)      r = (p[i] != 0);
    else if (mode == 1) r = (((const float*)p)[i] != 0.0f);
    else                r = (((const int*)p)[i] != 0);
    g_mask[i] = r;
}

// ---------------- fp32 -> fp16 conversion kernels ---------------------------
__global__ void tohalf_kernel(const float* __restrict__ src,
                              __half* __restrict__ hi, int n) {
    int i = (blockIdx.x * blockDim.x + threadIdx.x) * 4;
    if (i >= n) return;
    float4 v = *(const float4*)(src + i);
    __half2 a = __floats2half2_rn(v.x, v.y);
    __half2 b = __floats2half2_rn(v.z, v.w);
    *(__half2*)(hi + i)     = a;
    *(__half2*)(hi + i + 2) = b;
}

__global__ void split_w_kernel(const float* __restrict__ w0, const float* __restrict__ w1,
                               const float* __restrict__ w2, const float* __restrict__ w3,
                               __half* __restrict__ hi, __half* __restrict__ lo) {
    int z = blockIdx.z;
    const float* src = (z==0)?w0:(z==1)?w1:(z==2)?w2:w3;
    size_t off = (size_t)z * 1024 * 1024;
    int i = (blockIdx.x * blockDim.x + threadIdx.x) * 4;
    float4 v = *(const float4*)(src + i);
    float f[4] = {v.x, v.y, v.z, v.w};
    __half h[4], l[4];
    #pragma unroll
    for (int j = 0; j < 4; ++j) {
        h[j] = __float2half_rn(f[j]);
        l[j] = __float2half_rn(f[j] - __half2float(h[j]));
    }
    *(__half2*)(hi + off + i)     = __halves2half2(h[0], h[1]);
    *(__half2*)(hi + off + i + 2) = __halves2half2(h[2], h[3]);
    *(__half2*)(lo + off + i)     = __halves2half2(l[0], l[1]);
    *(__half2*)(lo + off + i + 2) = __halves2half2(l[2], l[3]);
}

// ---------------- mma / ldmatrix / cp.async primitives ----------------------
__device__ __forceinline__ void mma16816(float* c, const uint32_t* a, const uint32_t* b) {
    asm volatile(
        "mma.sync.aligned.m16n8k16.row.col.f32.f16.f16.f32 "
        "{%0,%1,%2,%3}, {%4,%5,%6,%7}, {%8,%9}, {%0,%1,%2,%3};"
        : "+f"(c[0]), "+f"(c[1]), "+f"(c[2]), "+f"(c[3])
        : "r"(a[0]), "r"(a[1]), "r"(a[2]), "r"(a[3]), "r"(b[0]), "r"(b[1]));
}
__device__ __forceinline__ void ldm_x4(uint32_t* r, uint32_t addr) {
    asm volatile("ldmatrix.sync.aligned.m8n8.x4.shared.b16 {%0,%1,%2,%3}, [%4];"
                 : "=r"(r[0]), "=r"(r[1]), "=r"(r[2]), "=r"(r[3]) : "r"(addr));
}
__device__ __forceinline__ void ldm_x4t(uint32_t* r, uint32_t addr) {
    asm volatile("ldmatrix.sync.aligned.m8n8.x4.trans.shared.b16 {%0,%1,%2,%3}, [%4];"
                 : "=r"(r[0]), "=r"(r[1]), "=r"(r[2]), "=r"(r[3]) : "r"(addr));
}
#define CP16(dst, src) \
    asm volatile("cp.async.cg.shared.global [%0], [%1], 16;" :: "r"(dst), "l"(src))
#define CP_COMMIT() asm volatile("cp.async.commit_group;" ::: "memory")
#define CP_WAIT(n)  asm volatile("cp.async.wait_group %0;" :: "n"(n) : "memory")

// ---------------- GEMM: C = A @ W^T + bias (fp16x2, 2-stage, occ 2) ---------
// A: fp16 hi only [M,1024]; W: fp16 hi/lo [N,1024]. BM=BN=128, BK=64.
// smem stage 48KB: A 16KB, Bh 16KB, Bl 16KB; 2 stages = 96KB -> 2 CTAs/SM.
// Single __syncthreads per iteration; prefetch distance 1 issued after sync.
#define GSTG 49152
#define GNIT 16

template <bool SPLIT>
__global__ __launch_bounds__(256, 2) void gemm_cp_kernel(
    const __half* __restrict__ Ag,
    const __half* __restrict__ Whb, const __half* __restrict__ Wlb, int woff,
    const float* b0, const float* b1, const float* b2,
    __half* C0h, __half* C0l,
    __half* C1h, __half* C1l,
    __half* C2h, __half* C2l,
    float* Cf)
{
    int z = blockIdx.z;
    const __half* Wh = Whb + (size_t)(woff + z) * 1024 * 1024;
    const __half* Wl = Wlb + (size_t)(woff + z) * 1024 * 1024;
    const float* bias = (z == 0) ? b0 : (z == 1) ? b1 : b2;
    __half* Ch = (z == 0) ? C0h : (z == 1) ? C1h : C2h;
    __half* Cl = (z == 0) ? C0l : (z == 1) ? C1l : C2l;

    extern __shared__ __align__(128) unsigned char smraw[];
    uint32_t sb = (uint32_t)__cvta_generic_to_shared(smraw);

    int t = threadIdx.x, lane = t & 31, warp = t >> 5;
    int wm = warp >> 2, wn = warp & 3;
    int m0 = blockIdx.y * 128, n0 = blockIdx.x * 128;

    int row = t >> 1, half = t & 1;
    const __half* srcA  = Ag + (size_t)(m0 + row) * 1024 + half * 32;
    const __half* srcBh = Wh + (size_t)(n0 + row) * 1024 + half * 32;
    const __half* srcBl = Wl + (size_t)(n0 + row) * 1024 + half * 32;
    uint32_t rxor = (uint32_t)((row & 7) << 4);
    uint32_t dA = sb + row * 128;

    auto issue = [&](int ch) {
        uint32_t base = dA + (uint32_t)(ch & 1) * GSTG;
        const __half* sa = srcA  + ch * 64;
        const __half* sh = srcBh + ch * 64;
        const __half* sl = srcBl + ch * 64;
        #pragma unroll
        for (int j = 0; j < 4; ++j) {
            uint32_t c = (uint32_t)(half * 64 + j * 16) ^ rxor;
            CP16(base + c,         sa + j * 8);
            CP16(base + 16384 + c, sh + j * 8);
            CP16(base + 32768 + c, sl + j * 8);
        }
    };

    float c[4][4][4] = {};
    uint32_t x = (uint32_t)((lane & 7) << 4);
    uint32_t arowb = (uint32_t)((wm * 64 + (lane & 15)) * 128);
    uint32_t acol = (uint32_t)((lane >> 4) << 4);
    uint32_t browb = (uint32_t)((wn * 32 + (lane & 7) + ((lane >> 4) << 3)) * 128);
    uint32_t bcol = (uint32_t)(((lane >> 3) & 1) << 4);

    issue(0); CP_COMMIT();

    for (int it = 0; it < GNIT; ++it) {
        CP_WAIT(0);          // stage it is the only group in flight
        __syncthreads();     // visible to all warps; all warps done with it-1
        if (it + 1 < GNIT) { issue(it + 1); CP_COMMIT(); }

        uint32_t Abase  = sb + (uint32_t)(it & 1) * GSTG;
        uint32_t Bhbase = Abase + 16384;
        uint32_t Blbase = Abase + 32768;
        #pragma unroll
        for (int kt = 0; kt < 4; ++kt) {
            uint32_t ac = ((uint32_t)(kt * 32) + acol) ^ x;
            uint32_t af[4][4];
            #pragma unroll
            for (int mi = 0; mi < 4; ++mi)
                ldm_x4(af[mi], Abase + arowb + mi * 16 * 128 + ac);
            uint32_t bc = ((uint32_t)(kt * 32) + bcol) ^ x;
            #pragma unroll
            for (int nip = 0; nip < 2; ++nip) {
                uint32_t baddr = browb + nip * 16 * 128 + bc;
                uint32_t bh4[4], bl4[4];
                ldm_x4(bh4, Bhbase + baddr);
                ldm_x4(bl4, Blbase + baddr);
                #pragma unroll
                for (int mi = 0; mi < 4; ++mi) {
                    mma16816(c[mi][2*nip],   af[mi], bh4);
                    mma16816(c[mi][2*nip],   af[mi], bl4);
                    mma16816(c[mi][2*nip+1], af[mi], bh4 + 2);
                    mma16816(c[mi][2*nip+1], af[mi], bl4 + 2);
                }
            }
        }
        __syncthreads();     // all warps done reading stage it before next overwrite
    }

    // epilogue
    int g = lane >> 2, cq = (lane & 3) * 2;
    #pragma unroll
    for (int mi = 0; mi < 4; ++mi) {
        int r0 = m0 + wm*64 + mi*16 + g;
        int r1 = r0 + 8;
        #pragma unroll
        for (int ni = 0; ni < 4; ++ni) {
            int col = n0 + wn*32 + ni*8 + cq;
            float b0v = __ldg(bias + col), b1v = __ldg(bias + col + 1);
            float v00 = c[mi][ni][0] + b0v, v01 = c[mi][ni][1] + b1v;
            float v10 = c[mi][ni][2] + b0v, v11 = c[mi][ni][3] + b1v;
            if (SPLIT) {
                int hh = col >> 6, hd = col & 63;
                int bi0 = r0 >> 11, s0 = r0 & 2047;
                int bi1 = r1 >> 11, s1 = r1 & 2047;
                size_t i0 = ((((size_t)bi0*NHEAD + hh)*SEQ) + s0)*HDIM + hd;
                size_t i1 = ((((size_t)bi1*NHEAD + hh)*SEQ) + s1)*HDIM + hd;
                __half2 h0 = __floats2half2_rn(v00, v01);
                __half2 h1 = __floats2half2_rn(v10, v11);
                *(__half2*)(Ch + i0) = h0;
                *(__half2*)(Ch + i1) = h1;
                if (Cl) {
                    __half2 l0 = __floats2half2_rn(v00 - __half2float(__low2half(h0)),
                                                   v01 - __half2float(__high2half(h0)));
                    __half2 l1 = __floats2half2_rn(v10 - __half2float(__low2half(h1)),
                                                   v11 - __half2float(__high2half(h1)));
                    *(__half2*)(Cl + i0) = l0;
                    *(__half2*)(Cl + i1) = l1;
                }
            } else {
                float2 v0 = {v00, v01}, v1 = {v10, v11};
                *(float2*)&Cf[(size_t)r0*DMODEL + col] = v0;
                *(float2*)&Cf[(size_t)r1*DMODEL + col] = v1;
            }
        }
    }
}

// ---------------- Flash attention (fp16x2, 2-stage ring, P-in-regs) ---------
// grid (SEQ/64, B*H), 128 threads (4 warps). Warp w owns query rows [w*16,+16).
// Single __syncthreads per key tile; prefetch distance 1 issued after sync.
#define ASTG 32768
#define KM_OFF (2*ASTG)
#define ATTN_SMEM (KM_OFF + 2*64*4)

__global__ __launch_bounds__(128, 3) void attn_cp_kernel(
    const __half* __restrict__ qhh,
    const __half* __restrict__ khh, const __half* __restrict__ khl,
    const __half* __restrict__ vhh, const __half* __restrict__ vhl,
    __half* __restrict__ obh)
{
    extern __shared__ __align__(128) unsigned char smraw[];
    float* kmf = (float*)(smraw + KM_OFF);

    int t = threadIdx.x, lane = t & 31, w = t >> 5;
    int g = lane >> 2, cq = (lane & 3) * 2;
    int qt = blockIdx.x, bh = blockIdx.y;
    int b = bh >> 4, h = bh & 15;
    int q0 = qt * 64;
    size_t bhoff = (size_t)bh * SEQ * HDIM;
    const __half* qb = qhh + bhoff + (size_t)q0 * HDIM;
    const unsigned char* mb = g_mask + b * SEQ;

    uint32_t sbse = (uint32_t)__cvta_generic_to_shared(smraw);
    uint32_t x = (uint32_t)((lane & 7) << 4);

    int row = t >> 1, half = t & 1;
    uint32_t rxor = (uint32_t)((row & 7) << 4);
    const __half* kvsrc[4] = {
        khh + bhoff + (size_t)row * HDIM + half * 32,
        khl + bhoff + (size_t)row * HDIM + half * 32,
        vhh + bhoff + (size_t)row * HDIM + half * 32,
        vhl + bhoff + (size_t)row * HDIM + half * 32 };

    auto issueKV = [&](int it2) {
        int st = it2 & 1;
        uint32_t base = sbse + st * ASTG + row * 128;
        size_t koff = (size_t)it2 * 64 * HDIM;
        #pragma unroll
        for (int rgn = 0; rgn < 4; ++rgn) {
            const __half* src = kvsrc[rgn] + koff;
            uint32_t db = base + rgn * 8192;
            #pragma unroll
            for (int j = 0; j < 4; ++j) {
                uint32_t c = (uint32_t)(half * 64 + j * 16) ^ rxor;
                CP16(db + c, src + j * 8);
            }
        }
        if (t < 64) kmf[st*64 + t] = mb[it2*64 + t] ? 0.0f : NEG_INF;
    };

    issueKV(0); CP_COMMIT();

    // stage Q (hi) through stage-1 buffer
    {
        uint32_t qdst = sbse + ASTG + row * 128;
        const uint4* gq = (const uint4*)(qb + row * HDIM + half * 32);
        #pragma unroll
        for (int j = 0; j < 4; ++j) {
            uint32_t c = (uint32_t)(half * 64 + j * 16) ^ rxor;
            uint4 v = gq[j];
            asm volatile("st.shared.v4.b32 [%0], {%1,%2,%3,%4};" ::
                "r"(qdst + c), "r"(v.x), "r"(v.y), "r"(v.z), "r"(v.w));
        }
    }
    __syncthreads();
    uint32_t qf[4][4];
    {
        uint32_t qrow = (uint32_t)(w*16 + (lane & 15));
        uint32_t qc = (uint32_t)((lane >> 4) << 4);
        #pragma unroll
        for (int kt = 0; kt < 4; ++kt) {
            uint32_t c = ((uint32_t)(kt*32) + qc) ^ x;
            ldm_x4(qf[kt], sbse + ASTG + qrow * 128 + c);
        }
    }
    __syncthreads();            // all warps have Q frags; stage 1 reusable

    float oc[8][4] = {};
    float m0r = NEG_INF, m1r = NEG_INF, l0r = 0.f, l1r = 0.f;
    uint32_t krow = (uint32_t)(lane & 7);
    uint32_t kq16 = (uint32_t)((lane >> 3) << 4);
    uint32_t vlr = (uint32_t)(lane & 15);
    uint32_t vsel = (uint32_t)((lane >> 4) << 4);

    const int NT = SEQ / 64;   // 32
    for (int it = 0; it < NT; ++it) {
        CP_WAIT(0);          // stage it is the only group in flight
        __syncthreads();     // visible; all warps done with stage it-1
        if (it + 1 < NT) { issueKV(it + 1); CP_COMMIT(); }

        uint32_t stage = sbse + (uint32_t)(it & 1) * ASTG;
        const uint32_t KhB = stage, KlB = stage + 8192;
        const uint32_t VhB = stage + 16384, VlB = stage + 24576;
        const float* km = kmf + (it & 1) * 64;

        // S = Qh Kh^T + Qh Kl^T  (16 rows x 64 keys per warp)
        float sc[8][4] = {};
        #pragma unroll
        for (int nt = 0; nt < 8; ++nt) {
            uint32_t rbase = ((uint32_t)(nt*8) + krow) * 128;
            #pragma unroll
            for (int ktp = 0; ktp < 2; ++ktp) {
                uint32_t c = ((uint32_t)(ktp*64) + kq16) ^ x;
                uint32_t kh4[4], kl4[4];
                ldm_x4(kh4, KhB + rbase + c);
                ldm_x4(kl4, KlB + rbase + c);
                mma16816(sc[nt], qf[2*ktp],   kh4);
                mma16816(sc[nt], qf[2*ktp],   kl4);
                mma16816(sc[nt], qf[2*ktp+1], kh4 + 2);
                mma16816(sc[nt], qf[2*ktp+1], kl4 + 2);
            }
        }

        // online softmax (rows g and g+8 of warp strip)
        float r0m = NEG_INF, r1m = NEG_INF;
        #pragma unroll
        for (int nt = 0; nt < 8; ++nt) {
            float a0 = km[nt*8 + cq], a1 = km[nt*8 + cq + 1];
            sc[nt][0] = sc[nt][0]*0.125f + a0;
            sc[nt][1] = sc[nt][1]*0.125f + a1;
            sc[nt][2] = sc[nt][2]*0.125f + a0;
            sc[nt][3] = sc[nt][3]*0.125f + a1;
            r0m = fmaxf(r0m, fmaxf(sc[nt][0], sc[nt][1]));
            r1m = fmaxf(r1m, fmaxf(sc[nt][2], sc[nt][3]));
        }
        r0m = fmaxf(r0m, __shfl_xor_sync(0xffffffffu, r0m, 1));
        r0m = fmaxf(r0m, __shfl_xor_sync(0xffffffffu, r0m, 2));
        r1m = fmaxf(r1m, __shfl_xor_sync(0xffffffffu, r1m, 1));
        r1m = fmaxf(r1m, __shfl_xor_sync(0xffffffffu, r1m, 2));
        float mn0 = fmaxf(m0r, r0m), mn1 = fmaxf(m1r, r1m);
        float ms0 = (mn0 == NEG_INF) ? 0.0f : mn0;
        float ms1 = (mn1 == NEG_INF) ? 0.0f : mn1;
        float al0 = __expf(m0r - ms0), al1 = __expf(m1r - ms1);
        m0r = mn0; m1r = mn1;

        // exp + pack P (fp16 hi) directly into PV A-fragment registers
        uint32_t ph[8], ph2[8];
        float rs0 = 0.f, rs1 = 0.f;
        #pragma unroll
        for (int nt = 0; nt < 8; ++nt) {
            float p0 = __expf(sc[nt][0] - ms0), p1 = __expf(sc[nt][1] - ms0);
            float p2 = __expf(sc[nt][2] - ms1), p3 = __expf(sc[nt][3] - ms1);
            rs0 += p0 + p1; rs1 += p2 + p3;
            __half2 hv0 = __floats2half2_rn(p0, p1);
            __half2 hv1 = __floats2half2_rn(p2, p3);
            ph[nt]  = *(uint32_t*)&hv0;
            ph2[nt] = *(uint32_t*)&hv1;
        }
        rs0 += __shfl_xor_sync(0xffffffffu, rs0, 1);
        rs0 += __shfl_xor_sync(0xffffffffu, rs0, 2);
        rs1 += __shfl_xor_sync(0xffffffffu, rs1, 1);
        rs1 += __shfl_xor_sync(0xffffffffu, rs1, 2);
        l0r = l0r * al0 + rs0;
        l1r = l1r * al1 + rs1;
        #pragma unroll
        for (int nt = 0; nt < 8; ++nt) {
            oc[nt][0] *= al0; oc[nt][1] *= al0;
            oc[nt][2] *= al1; oc[nt][3] *= al1;
        }

        // O += Ph Vh + Ph Vl
        #pragma unroll
        for (int kt = 0; kt < 4; ++kt) {
            uint32_t pa[4] = {ph[2*kt], ph2[2*kt], ph[2*kt+1], ph2[2*kt+1]};
            uint32_t vr = ((uint32_t)(kt*16) + vlr) * 128;
            #pragma unroll
            for (int ntp = 0; ntp < 4; ++ntp) {
                uint32_t c = ((uint32_t)(ntp*32) + vsel) ^ x;
                uint32_t vh4[4], vl4[4];
                ldm_x4t(vh4, VhB + vr + c);
                ldm_x4t(vl4, VlB + vr + c);
                mma16816(oc[2*ntp],   pa, vh4);
                mma16816(oc[2*ntp],   pa, vl4);
                mma16816(oc[2*ntp+1], pa, vh4 + 2);
                mma16816(oc[2*ntp+1], pa, vl4 + 2);
            }
        }
    }

    // epilogue: normalize, zero masked query rows, write (b,s,d) as fp16 hi
    int r0 = w*16 + g, r1 = r0 + 8;
    float inv0 = (mb[q0 + r0] && l0r > 0.f) ? 1.0f / l0r : 0.0f;
    float inv1 = (mb[q0 + r1] && l1r > 0.f) ? 1.0f / l1r : 0.0f;
    size_t base0 = ((size_t)b*SEQ + q0 + r0)*DMODEL + h*HDIM;
    size_t base1 = ((size_t)b*SEQ + q0 + r1)*DMODEL + h*HDIM;
    #pragma unroll
    for (int nt = 0; nt < 8; ++nt) {
        __half2 h0 = __floats2half2_rn(oc[nt][0]*inv0, oc[nt][1]*inv0);
        __half2 h1 = __floats2half2_rn(oc[nt][2]*inv1, oc[nt][3]*inv1);
        *(__half2*)(obh + base0 + nt*8 + cq) = h0;
        *(__half2*)(obh + base1 + nt*8 + cq) = h1;
    }
}

// ---------------- launch ----------------------------------------------------
extern "C" void kernel_launch(void* const* d_in, const int* in_sizes, int n_in,
                              void* d_out, int out_size) {
    const float* q    = (const float*)d_in[0];
    const unsigned char* mask = (const unsigned char*)d_in[1];
    const float* Wq   = (const float*)d_in[2];
    const float* bq   = (const float*)d_in[3];
    const float* Wk   = (const float*)d_in[4];
    const float* bk   = (const float*)d_in[5];
    const float* Wv   = (const float*)d_in[6];
    const float* bv   = (const float*)d_in[7];
    const float* Wo   = (const float*)d_in[8];
    const float* bo   = (const float*)d_in[9];
    float* out = (float*)d_out;

    __half *ah, *wh, *wl, *qhh, *khh, *khl, *vhh, *vhl, *oh;
    cudaGetSymbolAddress((void**)&ah,  g_ah);
    cudaGetSymbolAddress((void**)&wh,  g_wh);
    cudaGetSymbolAddress((void**)&wl,  g_wl);
    cudaGetSymbolAddress((void**)&qhh, g_qhh);
    cudaGetSymbolAddress((void**)&khh, g_khh);
    cudaGetSymbolAddress((void**)&khl, g_khl);
    cudaGetSymbolAddress((void**)&vhh, g_vhh);
    cudaGetSymbolAddress((void**)&vhl, g_vhl);
    cudaGetSymbolAddress((void**)&oh,  g_oh);

    detect_mask_kernel<<<1, 256>>>(mask);
    convert_mask_kernel<<<(BATCH*SEQ + 255) / 256, 256>>>(mask);

    tohalf_kernel<<<NELEM / 1024, 256>>>(q, ah, NELEM);
    split_w_kernel<<<dim3(1024, 1, 4), 256>>>(Wq, Wk, Wv, Wo, wh, wl);

    const int gemm_smem = 2 * GSTG;   // 98304 B -> 2 CTAs/SM
    static bool attr_done = false;
    if (!attr_done) {
        cudaFuncSetAttribute(gemm_cp_kernel<true>,
                             cudaFuncAttributeMaxDynamicSharedMemorySize, gemm_smem);
        cudaFuncSetAttribute(gemm_cp_kernel<false>,
                             cudaFuncAttributeMaxDynamicSharedMemorySize, gemm_smem);
        cudaFuncSetAttribute(attn_cp_kernel,
                             cudaFuncAttributeMaxDynamicSharedMemorySize, ATTN_SMEM);
        attr_done = true;
    }

    // fused QKV projections (Q -> hi only; K,V -> hi+lo)
    gemm_cp_kernel<true><<<dim3(8, 64, 3), 256, gemm_smem>>>(
        ah, wh, wl, 0, bq, bk, bv,
        qhh, nullptr, khh, khl, vhh, vhl, nullptr);

    attn_cp_kernel<<<dim3(SEQ / 64, BATCH * NHEAD), 128, ATTN_SMEM>>>(
        qhh, khh, khl, vhh, vhl, oh);

    // output projection -> fp32 out
    gemm_cp_kernel<false><<<dim3(8, 64, 1), 256, gemm_smem>>>(
        oh, wh, wl, 3, bo, bo, bo,
        nullptr, nullptr, nullptr, nullptr, nullptr, nullptr, out);
}

// round 10
// speedup vs baseline: 2.0311x; 1.1665x over previous
#include <cuda_runtime.h>
#include <cuda_fp16.h>
#include <cstdint>

// Problem constants
#define BATCH 4
#define SEQ   2048
#define DMODEL 1024
#define NHEAD 16
#define HDIM  64
#define MROWS (BATCH*SEQ)         // 8192

#define NEG_INF __int_as_float(0xff800000)
#define LOG2E 1.44269504f

// ---------------- scratch (device globals; no allocation allowed) ----------
#define NELEM (8192*1024)
__device__ __half g_ah[NELEM];                            // input x, fp16 hi only
__device__ __half g_wh[4*1024*1024], g_wl[4*1024*1024];   // Wq,Wk,Wv,Wo hi/lo
__device__ __half g_qhh[NELEM];                           // Q heads hi only
__device__ __half g_khh[NELEM], g_khl[NELEM];             // K heads hi/lo
__device__ __half g_vhh[NELEM], g_vhl[NELEM];             // V heads hi/lo
__device__ __half g_oh[NELEM];                            // attn out hi only
__device__ unsigned char g_mask[BATCH*SEQ];
__device__ int g_mode;

// ---------------- mask dtype detection + canonicalization ------------------
__global__ void detect_mask_kernel(const unsigned char* __restrict__ p) {
    __shared__ int s1, s3;
    if (threadIdx.x == 0) { s1 = 0; s3 = 0; }
    __syncthreads();
    int l1 = 0, l3 = 0;
    for (int i = threadIdx.x; i < BATCH*SEQ; i += blockDim.x) {
        unsigned char v = p[i];
        int m = i & 3;
        if (m == 1 && v) l1 = 1;
        if (m == 3 && v) l3 = 1;
    }
    if (l1) atomicOr(&s1, 1);
    if (l3) atomicOr(&s3, 1);
    __syncthreads();
    if (threadIdx.x == 0) g_mode = s1 ? 0 : (s3 ? 1 : 2);  // 0=u8, 1=f32, 2=i32
}

__global__ void convert_mask_kernel(const unsigned char* __restrict__ p) {
    int i = blockIdx.x * blockDim.x + threadIdx.x;
    if (i >= BATCH*SEQ) return;
    int mode = g_mode;
    unsigned char r;
    if (mode == 0)      r = (p[i] != 0);
    else if (mode == 1) r = (((const float*)p)[i] != 0.0f);
    else                r = (((const int*)p)[i] != 0);
    g_mask[i] = r;
}

// ---------------- fp32 -> fp16 conversion kernels ---------------------------
__global__ void tohalf_kernel(const float* __restrict__ src,
                              __half* __restrict__ hi, int n) {
    int i = (blockIdx.x * blockDim.x + threadIdx.x) * 4;
    if (i >= n) return;
    float4 v = *(const float4*)(src + i);
    __half2 a = __floats2half2_rn(v.x, v.y);
    __half2 b = __floats2half2_rn(v.z, v.w);
    *(__half2*)(hi + i)     = a;
    *(__half2*)(hi + i + 2) = b;
}

__global__ void split_w_kernel(const float* __restrict__ w0, const float* __restrict__ w1,
                               const float* __restrict__ w2, const float* __restrict__ w3,
                               __half* __restrict__ hi, __half* __restrict__ lo) {
    int z = blockIdx.z;
    const float* src = (z==0)?w0:(z==1)?w1:(z==2)?w2:w3;
    size_t off = (size_t)z * 1024 * 1024;
    int i = (blockIdx.x * blockDim.x + threadIdx.x) * 4;
    float4 v = *(const float4*)(src + i);
    float f[4] = {v.x, v.y, v.z, v.w};
    __half h[4], l[4];
    #pragma unroll
    for (int j = 0; j < 4; ++j) {
        h[j] = __float2half_rn(f[j]);
        l[j] = __float2half_rn(f[j] - __half2float(h[j]));
    }
    *(__half2*)(hi + off + i)     = __halves2half2(h[0], h[1]);
    *(__half2*)(hi + off + i + 2) = __halves2half2(h[2], h[3]);
    *(__half2*)(lo + off + i)     = __halves2half2(l[0], l[1]);
    *(__half2*)(lo + off + i + 2) = __halves2half2(l[2], l[3]);
}

// ---------------- mma / ldmatrix / cp.async primitives ----------------------
__device__ __forceinline__ void mma16816(float* c, const uint32_t* a, const uint32_t* b) {
    asm volatile(
        "mma.sync.aligned.m16n8k16.row.col.f32.f16.f16.f32 "
        "{%0,%1,%2,%3}, {%4,%5,%6,%7}, {%8,%9}, {%0,%1,%2,%3};"
        : "+f"(c[0]), "+f"(c[1]), "+f"(c[2]), "+f"(c[3])
        : "r"(a[0]), "r"(a[1]), "r"(a[2]), "r"(a[3]), "r"(b[0]), "r"(b[1]));
}
__device__ __forceinline__ void ldm_x4(uint32_t* r, uint32_t addr) {
    asm volatile("ldmatrix.sync.aligned.m8n8.x4.shared.b16 {%0,%1,%2,%3}, [%4];"
                 : "=r"(r[0]), "=r"(r[1]), "=r"(r[2]), "=r"(r[3]) : "r"(addr));
}
__device__ __forceinline__ void ldm_x4t(uint32_t* r, uint32_t addr) {
    asm volatile("ldmatrix.sync.aligned.m8n8.x4.trans.shared.b16 {%0,%1,%2,%3}, [%4];"
                 : "=r"(r[0]), "=r"(r[1]), "=r"(r[2]), "=r"(r[3]) : "r"(addr));
}
#define CP16(dst, src) \
    asm volatile("cp.async.cg.shared.global [%0], [%1], 16;" :: "r"(dst), "l"(src))
#define CP_COMMIT() asm volatile("cp.async.commit_group;" ::: "memory")
#define CP_WAIT(n)  asm volatile("cp.async.wait_group %0;" :: "n"(n) : "memory")

// ---------------- GEMM: C = A @ W^T + bias (fp16x2, 2-stage, occ 2) ---------
// Single __syncthreads per iteration (the top sync both publishes stage `it`
// and guarantees stage it-1 reads finished before issue(it+1) overwrites it).
#define GSTG 49152
#define GNIT 16

template <bool SPLIT>
__global__ __launch_bounds__(256, 2) void gemm_cp_kernel(
    const __half* __restrict__ Ag,
    const __half* __restrict__ Whb, const __half* __restrict__ Wlb, int woff,
    const float* b0, const float* b1, const float* b2,
    __half* C0h, __half* C0l,
    __half* C1h, __half* C1l,
    __half* C2h, __half* C2l,
    float* Cf)
{
    int z = blockIdx.z;
    const __half* Wh = Whb + (size_t)(woff + z) * 1024 * 1024;
    const __half* Wl = Wlb + (size_t)(woff + z) * 1024 * 1024;
    const float* bias = (z == 0) ? b0 : (z == 1) ? b1 : b2;
    __half* Ch = (z == 0) ? C0h : (z == 1) ? C1h : C2h;
    __half* Cl = (z == 0) ? C0l : (z == 1) ? C1l : C2l;

    extern __shared__ __align__(128) unsigned char smraw[];
    uint32_t sb = (uint32_t)__cvta_generic_to_shared(smraw);

    int t = threadIdx.x, lane = t & 31, warp = t >> 5;
    int wm = warp >> 2, wn = warp & 3;
    int m0 = blockIdx.y * 128, n0 = blockIdx.x * 128;

    int row = t >> 1, half = t & 1;
    const __half* srcA  = Ag + (size_t)(m0 + row) * 1024 + half * 32;
    const __half* srcBh = Wh + (size_t)(n0 + row) * 1024 + half * 32;
    const __half* srcBl = Wl + (size_t)(n0 + row) * 1024 + half * 32;
    uint32_t rxor = (uint32_t)((row & 7) << 4);
    uint32_t dA = sb + row * 128;

    auto issue = [&](int ch) {
        uint32_t base = dA + (uint32_t)(ch & 1) * GSTG;
        const __half* sa = srcA  + ch * 64;
        const __half* sh = srcBh + ch * 64;
        const __half* sl = srcBl + ch * 64;
        #pragma unroll
        for (int j = 0; j < 4; ++j) {
            uint32_t c = (uint32_t)(half * 64 + j * 16) ^ rxor;
            CP16(base + c,         sa + j * 8);
            CP16(base + 16384 + c, sh + j * 8);
            CP16(base + 32768 + c, sl + j * 8);
        }
    };

    float c[4][4][4] = {};
    uint32_t x = (uint32_t)((lane & 7) << 4);
    uint32_t arowb = (uint32_t)((wm * 64 + (lane & 15)) * 128);
    uint32_t acol = (uint32_t)((lane >> 4) << 4);
    uint32_t browb = (uint32_t)((wn * 32 + (lane & 7) + ((lane >> 4) << 3)) * 128);
    uint32_t bcol = (uint32_t)(((lane >> 3) & 1) << 4);

    issue(0); CP_COMMIT();

    for (int it = 0; it < GNIT; ++it) {
        CP_WAIT(0);
        __syncthreads();
        if (it + 1 < GNIT) { issue(it + 1); CP_COMMIT(); }

        uint32_t Abase  = sb + (uint32_t)(it & 1) * GSTG;
        uint32_t Bhbase = Abase + 16384;
        uint32_t Blbase = Abase + 32768;
        #pragma unroll
        for (int kt = 0; kt < 4; ++kt) {
            uint32_t ac = ((uint32_t)(kt * 32) + acol) ^ x;
            uint32_t af[4][4];
            #pragma unroll
            for (int mi = 0; mi < 4; ++mi)
                ldm_x4(af[mi], Abase + arowb + mi * 16 * 128 + ac);
            uint32_t bc = ((uint32_t)(kt * 32) + bcol) ^ x;
            #pragma unroll
            for (int nip = 0; nip < 2; ++nip) {
                uint32_t baddr = browb + nip * 16 * 128 + bc;
                uint32_t bh4[4], bl4[4];
                ldm_x4(bh4, Bhbase + baddr);
                ldm_x4(bl4, Blbase + baddr);
                #pragma unroll
                for (int mi = 0; mi < 4; ++mi) {
                    mma16816(c[mi][2*nip],   af[mi], bh4);
                    mma16816(c[mi][2*nip],   af[mi], bl4);
                    mma16816(c[mi][2*nip+1], af[mi], bh4 + 2);
                    mma16816(c[mi][2*nip+1], af[mi], bl4 + 2);
                }
            }
        }
    }

    // epilogue
    int g = lane >> 2, cq = (lane & 3) * 2;
    #pragma unroll
    for (int mi = 0; mi < 4; ++mi) {
        int r0 = m0 + wm*64 + mi*16 + g;
        int r1 = r0 + 8;
        #pragma unroll
        for (int ni = 0; ni < 4; ++ni) {
            int col = n0 + wn*32 + ni*8 + cq;
            float b0v = __ldg(bias + col), b1v = __ldg(bias + col + 1);
            float v00 = c[mi][ni][0] + b0v, v01 = c[mi][ni][1] + b1v;
            float v10 = c[mi][ni][2] + b0v, v11 = c[mi][ni][3] + b1v;
            if (SPLIT) {
                int hh = col >> 6, hd = col & 63;
                int bi0 = r0 >> 11, s0 = r0 & 2047;
                int bi1 = r1 >> 11, s1 = r1 & 2047;
                size_t i0 = ((((size_t)bi0*NHEAD + hh)*SEQ) + s0)*HDIM + hd;
                size_t i1 = ((((size_t)bi1*NHEAD + hh)*SEQ) + s1)*HDIM + hd;
                __half2 h0 = __floats2half2_rn(v00, v01);
                __half2 h1 = __floats2half2_rn(v10, v11);
                *(__half2*)(Ch + i0) = h0;
                *(__half2*)(Ch + i1) = h1;
                if (Cl) {
                    __half2 l0 = __floats2half2_rn(v00 - __half2float(__low2half(h0)),
                                                   v01 - __half2float(__high2half(h0)));
                    __half2 l1 = __floats2half2_rn(v10 - __half2float(__low2half(h1)),
                                                   v11 - __half2float(__high2half(h1)));
                    *(__half2*)(Cl + i0) = l0;
                    *(__half2*)(Cl + i1) = l1;
                }
            } else {
                float2 v0 = {v00, v01}, v1 = {v10, v11};
                *(float2*)&Cf[(size_t)r0*DMODEL + col] = v0;
                *(float2*)&Cf[(size_t)r1*DMODEL + col] = v1;
            }
        }
    }
}

// ---------------- Flash attention (fp16x2, 128-q tile, 8 warps) -------------
// grid (SEQ/128, B*H), 256 threads. Warp w owns query rows [w*16, w*16+16).
// K/V smem per stage: {Kh,Kl,Vh,Vl} x 64 rows x 128B, swizzled; 2 stages=64KB.
// Halves KV global traffic vs 64-q tile. exp2-domain softmax (scale folded).
#define ASTG 32768
#define KM_OFF (2*ASTG)
#define ATTN_SMEM (KM_OFF + 2*64*4)

__global__ __launch_bounds__(256, 2) void attn_cp_kernel(
    const __half* __restrict__ qhh,
    const __half* __restrict__ khh, const __half* __restrict__ khl,
    const __half* __restrict__ vhh, const __half* __restrict__ vhl,
    __half* __restrict__ obh)
{
    extern __shared__ __align__(128) unsigned char smraw[];
    float* kmf = (float*)(smraw + KM_OFF);

    int t = threadIdx.x, lane = t & 31, w = t >> 5;
    int g = lane >> 2, cq = (lane & 3) * 2;
    int qt = blockIdx.x, bh = blockIdx.y;
    int b = bh >> 4, h = bh & 15;
    int q0 = qt * 128;
    size_t bhoff = (size_t)bh * SEQ * HDIM;
    const __half* qb = qhh + bhoff + (size_t)q0 * HDIM;
    const unsigned char* mb = g_mask + b * SEQ;

    uint32_t sbse = (uint32_t)__cvta_generic_to_shared(smraw);
    uint32_t x = (uint32_t)((lane & 7) << 4);

    // KV loading: 256 threads, each covers 32B of one row per region
    int rowq = t >> 2, part = t & 3;
    uint32_t rxq = (uint32_t)((rowq & 7) << 4);
    const __half* kvsrc[4] = {
        khh + bhoff + (size_t)rowq * HDIM + part * 16,
        khl + bhoff + (size_t)rowq * HDIM + part * 16,
        vhh + bhoff + (size_t)rowq * HDIM + part * 16,
        vhl + bhoff + (size_t)rowq * HDIM + part * 16 };

    auto issueKV = [&](int it2) {
        int st = it2 & 1;
        uint32_t base = sbse + st * ASTG + rowq * 128;
        size_t koff = (size_t)it2 * 64 * HDIM;
        #pragma unroll
        for (int rgn = 0; rgn < 4; ++rgn) {
            const __half* src = kvsrc[rgn] + koff;
            uint32_t db = base + rgn * 8192;
            #pragma unroll
            for (int j = 0; j < 2; ++j) {
                uint32_t c = (uint32_t)(part * 32 + j * 16) ^ rxq;
                CP16(db + c, src + j * 8);
            }
        }
        if (t < 64) kmf[st*64 + t] = mb[it2*64 + t] ? 0.0f : NEG_INF;
    };

    issueKV(0); CP_COMMIT();

    // stage Q (hi, 128 rows) through stage-1 buffer (spans its Kh+Kl regions)
    {
        int rq = t >> 1, hq = t & 1;
        uint32_t qdst = sbse + ASTG + rq * 128;
        const uint4* gq = (const uint4*)(qb + rq * HDIM + hq * 32);
        uint32_t rx = (uint32_t)((rq & 7) << 4);
        #pragma unroll
        for (int j = 0; j < 4; ++j) {
            uint32_t c = (uint32_t)(hq * 64 + j * 16) ^ rx;
            uint4 v = gq[j];
            asm volatile("st.shared.v4.b32 [%0], {%1,%2,%3,%4};" ::
                "r"(qdst + c), "r"(v.x), "r"(v.y), "r"(v.z), "r"(v.w));
        }
    }
    __syncthreads();
    uint32_t qf[4][4];
    {
        uint32_t qrow = (uint32_t)(w*16 + (lane & 15));
        uint32_t qc = (uint32_t)((lane >> 4) << 4);
        #pragma unroll
        for (int kt = 0; kt < 4; ++kt) {
            uint32_t c = ((uint32_t)(kt*32) + qc) ^ x;
            ldm_x4(qf[kt], sbse + ASTG + qrow * 128 + c);
        }
    }
    __syncthreads();            // all warps have Q frags; stage 1 reusable

    float oc[8][4] = {};
    float m0r = NEG_INF, m1r = NEG_INF, l0r = 0.f, l1r = 0.f;
    uint32_t krow = (uint32_t)(lane & 7);
    uint32_t kq16 = (uint32_t)((lane >> 3) << 4);
    uint32_t vlr = (uint32_t)(lane & 15);
    uint32_t vsel = (uint32_t)((lane >> 4) << 4);
    const float SC2 = 0.125f * LOG2E;   // score scale folded with log2(e)

    const int NT = SEQ / 64;   // 32
    for (int it = 0; it < NT; ++it) {
        CP_WAIT(0);
        __syncthreads();     // stage it visible; all warps done with it-1
        if (it + 1 < NT) { issueKV(it + 1); CP_COMMIT(); }

        uint32_t stage = sbse + (uint32_t)(it & 1) * ASTG;
        const uint32_t KhB = stage, KlB = stage + 8192;
        const uint32_t VhB = stage + 16384, VlB = stage + 24576;
        const float* km = kmf + (it & 1) * 64;

        // S = Qh Kh^T + Qh Kl^T  (16 rows x 64 keys per warp)
        float sc[8][4] = {};
        #pragma unroll
        for (int nt = 0; nt < 8; ++nt) {
            uint32_t rbase = ((uint32_t)(nt*8) + krow) * 128;
            #pragma unroll
            for (int ktp = 0; ktp < 2; ++ktp) {
                uint32_t c = ((uint32_t)(ktp*64) + kq16) ^ x;
                uint32_t kh4[4], kl4[4];
                ldm_x4(kh4, KhB + rbase + c);
                ldm_x4(kl4, KlB + rbase + c);
                mma16816(sc[nt], qf[2*ktp],   kh4);
                mma16816(sc[nt], qf[2*ktp],   kl4);
                mma16816(sc[nt], qf[2*ktp+1], kh4 + 2);
                mma16816(sc[nt], qf[2*ktp+1], kl4 + 2);
            }
        }

        // online softmax in exp2 domain (rows g and g+8 of warp strip)
        float r0m = NEG_INF, r1m = NEG_INF;
        #pragma unroll
        for (int nt = 0; nt < 8; ++nt) {
            float a0 = km[nt*8 + cq], a1 = km[nt*8 + cq + 1];
            sc[nt][0] = sc[nt][0]*SC2 + a0;
            sc[nt][1] = sc[nt][1]*SC2 + a1;
            sc[nt][2] = sc[nt][2]*SC2 + a0;
            sc[nt][3] = sc[nt][3]*SC2 + a1;
            r0m = fmaxf(r0m, fmaxf(sc[nt][0], sc[nt][1]));
            r1m = fmaxf(r1m, fmaxf(sc[nt][2], sc[nt][3]));
        }
        r0m = fmaxf(r0m, __shfl_xor_sync(0xffffffffu, r0m, 1));
        r0m = fmaxf(r0m, __shfl_xor_sync(0xffffffffu, r0m, 2));
        r1m = fmaxf(r1m, __shfl_xor_sync(0xffffffffu, r1m, 1));
        r1m = fmaxf(r1m, __shfl_xor_sync(0xffffffffu, r1m, 2));
        float mn0 = fmaxf(m0r, r0m), mn1 = fmaxf(m1r, r1m);
        float ms0 = (mn0 == NEG_INF) ? 0.0f : mn0;
        float ms1 = (mn1 == NEG_INF) ? 0.0f : mn1;
        float al0 = exp2f(m0r - ms0), al1 = exp2f(m1r - ms1);
        m0r = mn0; m1r = mn1;

        // exp2 + pack P (fp16 hi) directly into PV A-fragment registers
        uint32_t ph[8], ph2[8];
        float rs0 = 0.f, rs1 = 0.f;
        #pragma unroll
        for (int nt = 0; nt < 8; ++nt) {
            float p0 = exp2f(sc[nt][0] - ms0), p1 = exp2f(sc[nt][1] - ms0);
            float p2 = exp2f(sc[nt][2] - ms1), p3 = exp2f(sc[nt][3] - ms1);
            rs0 += p0 + p1; rs1 += p2 + p3;
            __half2 hv0 = __floats2half2_rn(p0, p1);
            __half2 hv1 = __floats2half2_rn(p2, p3);
            ph[nt]  = *(uint32_t*)&hv0;
            ph2[nt] = *(uint32_t*)&hv1;
        }
        rs0 += __shfl_xor_sync(0xffffffffu, rs0, 1);
        rs0 += __shfl_xor_sync(0xffffffffu, rs0, 2);
        rs1 += __shfl_xor_sync(0xffffffffu, rs1, 1);
        rs1 += __shfl_xor_sync(0xffffffffu, rs1, 2);
        l0r = l0r * al0 + rs0;
        l1r = l1r * al1 + rs1;
        #pragma unroll
        for (int nt = 0; nt < 8; ++nt) {
            oc[nt][0] *= al0; oc[nt][1] *= al0;
            oc[nt][2] *= al1; oc[nt][3] *= al1;
        }

        // O += Ph Vh + Ph Vl
        #pragma unroll
        for (int kt = 0; kt < 4; ++kt) {
            uint32_t pa[4] = {ph[2*kt], ph2[2*kt], ph[2*kt+1], ph2[2*kt+1]};
            uint32_t vr = ((uint32_t)(kt*16) + vlr) * 128;
            #pragma unroll
            for (int ntp = 0; ntp < 4; ++ntp) {
                uint32_t c = ((uint32_t)(ntp*32) + vsel) ^ x;
                uint32_t vh4[4], vl4[4];
                ldm_x4t(vh4, VhB + vr + c);
                ldm_x4t(vl4, VlB + vr + c);
                mma16816(oc[2*ntp],   pa, vh4);
                mma16816(oc[2*ntp],   pa, vl4);
                mma16816(oc[2*ntp+1], pa, vh4 + 2);
                mma16816(oc[2*ntp+1], pa, vl4 + 2);
            }
        }
    }

    // epilogue: normalize, zero masked query rows, write (b,s,d) as fp16 hi
    int r0 = w*16 + g, r1 = r0 + 8;
    float inv0 = (mb[q0 + r0] && l0r > 0.f) ? 1.0f / l0r : 0.0f;
    float inv1 = (mb[q0 + r1] && l1r > 0.f) ? 1.0f / l1r : 0.0f;
    size_t base0 = ((size_t)b*SEQ + q0 + r0)*DMODEL + h*HDIM;
    size_t base1 = ((size_t)b*SEQ + q0 + r1)*DMODEL + h*HDIM;
    #pragma unroll
    for (int nt = 0; nt < 8; ++nt) {
        __half2 h0 = __floats2half2_rn(oc[nt][0]*inv0, oc[nt][1]*inv0);
        __half2 h1 = __floats2half2_rn(oc[nt][2]*inv1, oc[nt][3]*inv1);
        *(__half2*)(obh + base0 + nt*8 + cq) = h0;
        *(__half2*)(obh + base1 + nt*8 + cq) = h1;
    }
}

// ---------------- launch ----------------------------------------------------
extern "C" void kernel_launch(void* const* d_in, const int* in_sizes, int n_in,
                              void* d_out, int out_size) {
    const float* q    = (const float*)d_in[0];
    const unsigned char* mask = (const unsigned char*)d_in[1];
    const float* Wq   = (const float*)d_in[2];
    const float* bq   = (const float*)d_in[3];
    const float* Wk   = (const float*)d_in[4];
    const float* bk   = (const float*)d_in[5];
    const float* Wv   = (const float*)d_in[6];
    const float* bv   = (const float*)d_in[7];
    const float* Wo   = (const float*)d_in[8];
    const float* bo   = (const float*)d_in[9];
    float* out = (float*)d_out;

    __half *ah, *wh, *wl, *qhh, *khh, *khl, *vhh, *vhl, *oh;
    cudaGetSymbolAddress((void**)&ah,  g_ah);
    cudaGetSymbolAddress((void**)&wh,  g_wh);
    cudaGetSymbolAddress((void**)&wl,  g_wl);
    cudaGetSymbolAddress((void**)&qhh, g_qhh);
    cudaGetSymbolAddress((void**)&khh, g_khh);
    cudaGetSymbolAddress((void**)&khl, g_khl);
    cudaGetSymbolAddress((void**)&vhh, g_vhh);
    cudaGetSymbolAddress((void**)&vhl, g_vhl);
    cudaGetSymbolAddress((void**)&oh,  g_oh);

    detect_mask_kernel<<<1, 256>>>(mask);
    convert_mask_kernel<<<(BATCH*SEQ + 255) / 256, 256>>>(mask);

    tohalf_kernel<<<NELEM / 1024, 256>>>(q, ah, NELEM);
    split_w_kernel<<<dim3(1024, 1, 4), 256>>>(Wq, Wk, Wv, Wo, wh, wl);

    const int gemm_smem = 2 * GSTG;   // 98304 B -> 2 CTAs/SM
    static bool attr_done = false;
    if (!attr_done) {
        cudaFuncSetAttribute(gemm_cp_kernel<true>,
                             cudaFuncAttributeMaxDynamicSharedMemorySize, gemm_smem);
        cudaFuncSetAttribute(gemm_cp_kernel<false>,
                             cudaFuncAttributeMaxDynamicSharedMemorySize, gemm_smem);
        cudaFuncSetAttribute(attn_cp_kernel,
                             cudaFuncAttributeMaxDynamicSharedMemorySize, ATTN_SMEM);
        attr_done = true;
    }

    // fused QKV projections (Q -> hi only; K,V -> hi+lo)
    gemm_cp_kernel<true><<<dim3(8, 64, 3), 256, gemm_smem>>>(
        ah, wh, wl, 0, bq, bk, bv,
        qhh, nullptr, khh, khl, vhh, vhl, nullptr);

    attn_cp_kernel<<<dim3(SEQ / 128, BATCH * NHEAD), 256, ATTN_SMEM>>>(
        qhh, khh, khl, vhh, vhl, oh);

    // output projection -> fp32 out
    gemm_cp_kernel<false><<<dim3(8, 64, 1), 256, gemm_smem>>>(
        oh, wh, wl, 3, bo, bo, bo,
        nullptr, nullptr, nullptr, nullptr, nullptr, nullptr, out);
}